// round 2
// baseline (speedup 1.0000x reference)
#include <cuda_runtime.h>
#include <cuda_bf16.h>
#include <math.h>

// Problem constants
#define NU 100000
#define NI 20000
#define ND 64
#define NH 128
#define NB 64

// Output layout (flattened concat of the returned tuple):
// likes  [64,20000] @ 0
// sim    [64,64]    @ 1280000
// rated  [64,20000] @ 1284096
// popular[20000]    @ 2564096
#define OFF_LIKES 0
#define OFF_SIM   1280000
#define OFF_RATED 1284096
#define OFF_POP   2564096

// Scratch (device globals — no allocation allowed)
__device__ float g_au[2][NB * NH];        // per-head: eu@Wu + b0  (bias folded)
__device__ float g_C[2][NI * NH];         // per-head: ei@Wi
__device__ float g_Cp[NI * NH];           // popular: relu(ei@pW0 + pb0)

// ---------------------------------------------------------------------------
// prep_user: block 0 -> au[likes], block 1 -> au[rated], block 2 -> sim
// ---------------------------------------------------------------------------
__global__ __launch_bounds__(256) void prep_user(
    const int* __restrict__ users, const float* __restrict__ ue,
    const float* __restrict__ lW0, const float* __restrict__ lb0,
    const float* __restrict__ rW0, const float* __restrict__ rb0,
    float* __restrict__ out_sim)
{
    __shared__ float eu_s[NB][ND + 1];
    __shared__ float inv[NB];
    int tid = threadIdx.x;

    for (int idx = tid; idx < NB * ND; idx += 256) {
        int b = idx >> 6, d = idx & 63;
        eu_s[b][d] = ue[users[b] * ND + d];
    }
    __syncthreads();

    int blk = blockIdx.x;
    if (blk < 2) {
        const float* W0 = (blk == 0) ? lW0 : rW0;
        const float* b0 = (blk == 0) ? lb0 : rb0;
        for (int o = tid; o < NB * NH; o += 256) {
            int b = o >> 7, h = o & 127;
            float acc = b0[h];
#pragma unroll
            for (int d = 0; d < ND; d++)
                acc += eu_s[b][d] * W0[d * NH + h];
            g_au[blk][o] = acc;
        }
    } else {
        for (int b = tid; b < NB; b += 256) {
            float s = 0.f;
#pragma unroll
            for (int d = 0; d < ND; d++) { float v = eu_s[b][d]; s += v * v; }
            inv[b] = rsqrtf(fmaxf(s, 1e-12f));
        }
        __syncthreads();
        for (int o = tid; o < NB * NB; o += 256) {
            int a = o >> 6, b = o & 63;
            float s = 0.f;
#pragma unroll
            for (int d = 0; d < ND; d++)
                s += eu_s[a][d] * eu_s[b][d];
            out_sim[o] = -(s * inv[a] * inv[b]);
        }
    }
}

// ---------------------------------------------------------------------------
// prep_items: C_likes = ei@Wi_l, C_rated = ei@Wi_r, C_pop = relu(ei@pW0+pb0)
// 64 items per block.
// ---------------------------------------------------------------------------
__global__ __launch_bounds__(256) void prep_items(
    const float* __restrict__ ie,
    const float* __restrict__ lW0, const float* __restrict__ rW0,
    const float* __restrict__ pW0, const float* __restrict__ pb0)
{
    __shared__ float ei_s[64][ND + 1];
    int tid = threadIdx.x;
    int i0 = blockIdx.x * 64;

    for (int idx = tid; idx < 64 * ND; idx += 256) {
        int ii = idx >> 6, d = idx & 63;
        int i = i0 + ii;
        ei_s[ii][d] = (i < NI) ? ie[i * ND + d] : 0.f;
    }
    __syncthreads();

    for (int o = tid; o < 64 * NH; o += 256) {
        int ii = o >> 7, h = o & 127;
        int i = i0 + ii;
        if (i >= NI) continue;
        float al = 0.f, ar = 0.f, ap = pb0[h];
#pragma unroll
        for (int d = 0; d < ND; d++) {
            float e = ei_s[ii][d];
            al += e * lW0[(ND + d) * NH + h];
            ar += e * rW0[(ND + d) * NH + h];
            ap += e * pW0[d * NH + h];
        }
        g_C[0][i * NH + h] = al;
        g_C[1][i * NH + h] = ar;
        g_Cp[i * NH + h] = fmaxf(ap, 0.f);
    }
}

// ---------------------------------------------------------------------------
// main_gemm: fused layer1 GEMM + layer2 dot + sigmoid.
// Heads (bx < 20000): tile = 8 users x 16 items = 128 rows; A = relu(au+C)
// Popular (bx >= 20000): tile = 128 items; A = C_pop (already relu'd)
// 256 threads (16x16), 8x8 register blocking, K=128 in 4 chunks of 32.
// ---------------------------------------------------------------------------
__global__ __launch_bounds__(256, 2) void main_gemm(
    const float* __restrict__ lW1, const float* __restrict__ lb1,
    const float* __restrict__ lW2, const float* __restrict__ lb2,
    const float* __restrict__ rW1, const float* __restrict__ rb1,
    const float* __restrict__ rW2, const float* __restrict__ rb2,
    const float* __restrict__ pW1, const float* __restrict__ pb1,
    const float* __restrict__ pW2, const float* __restrict__ pb2,
    float* __restrict__ out)
{
    __shared__ float au_s[8][129];
    __shared__ float c_s[16][129];
    __shared__ float As[32][132];
    __shared__ float Bs[32][128];
    __shared__ float b1s[128];
    __shared__ float w2s[128];
    __shared__ float b2s;

    int tid = threadIdx.x;
    int tx = tid & 15, ty = tid >> 4;
    int bx = blockIdx.x;

    int head, i0, b0u;
    const float *W1, *b1, *W2, *b2;
    if (bx < 20000) {
        head = (bx < 10000) ? 0 : 1;
        int t = bx - head * 10000;
        b0u = (t & 7) * 8;      // user tile (8 users)
        i0  = (t >> 3) * 16;    // item tile (16 items)
        if (head == 0) { W1 = lW1; b1 = lb1; W2 = lW2; b2 = lb2; }
        else           { W1 = rW1; b1 = rb1; W2 = rW2; b2 = rb2; }
    } else {
        head = 2;
        i0 = (bx - 20000) * 128;
        b0u = 0;
        W1 = pW1; b1 = pb1; W2 = pW2; b2 = pb2;
    }

    // Stage per-block constants
    if (head < 2) {
        for (int idx = tid; idx < 8 * NH; idx += 256) {
            int bb = idx >> 7, k = idx & 127;
            au_s[bb][k] = g_au[head][(b0u + bb) * NH + k];
        }
        for (int idx = tid; idx < 16 * NH; idx += 256) {
            int ii = idx >> 7, k = idx & 127;
            c_s[ii][k] = g_C[head][(i0 + ii) * NH + k];
        }
    }
    if (tid < 128) { b1s[tid] = b1[tid]; w2s[tid] = W2[tid]; }
    if (tid == 0) b2s = b2[0];
    __syncthreads();

    float acc[8][8];
#pragma unroll
    for (int mi = 0; mi < 8; mi++)
#pragma unroll
        for (int ni = 0; ni < 8; ni++) acc[mi][ni] = 0.f;

    for (int kc = 0; kc < 4; kc++) {
        // Build A chunk (transposed: As[k][row])
        if (head < 2) {
            for (int idx = tid; idx < 32 * 128; idx += 256) {
                int k = idx >> 7, r = idx & 127;
                float v = au_s[r & 7][kc * 32 + k] + c_s[r >> 3][kc * 32 + k];
                As[k][r] = fmaxf(v, 0.f);
            }
        } else {
            for (int idx = tid; idx < 128 * 32; idx += 256) {
                int r = idx >> 5, k = idx & 31;
                int i = i0 + r;
                As[k][r] = (i < NI) ? g_Cp[i * NH + kc * 32 + k] : 0.f;
            }
        }
        // Load W1 chunk
        for (int idx = tid; idx < 32 * 128; idx += 256) {
            int k = idx >> 7, c = idx & 127;
            Bs[k][c] = W1[(kc * 32 + k) * NH + c];
        }
        __syncthreads();

#pragma unroll
        for (int k = 0; k < 32; k++) {
            float a[8], bv[8];
            *(float4*)&a[0]  = *(const float4*)&As[k][ty * 8];
            *(float4*)&a[4]  = *(const float4*)&As[k][ty * 8 + 4];
            *(float4*)&bv[0] = *(const float4*)&Bs[k][tx * 8];
            *(float4*)&bv[4] = *(const float4*)&Bs[k][tx * 8 + 4];
#pragma unroll
            for (int mi = 0; mi < 8; mi++)
#pragma unroll
                for (int ni = 0; ni < 8; ni++)
                    acc[mi][ni] += a[mi] * bv[ni];
        }
        __syncthreads();
    }

    // Epilogue: h1 = relu(acc + b1); z = h1 @ W2; sigmoid
    float zr[8];
#pragma unroll
    for (int mi = 0; mi < 8; mi++) {
        float p = 0.f;
#pragma unroll
        for (int ni = 0; ni < 8; ni++) {
            int c = tx * 8 + ni;
            float h = fmaxf(acc[mi][ni] + b1s[c], 0.f);
            p += h * w2s[c];
        }
        p += __shfl_xor_sync(0xffffffffu, p, 8);
        p += __shfl_xor_sync(0xffffffffu, p, 4);
        p += __shfl_xor_sync(0xffffffffu, p, 2);
        p += __shfl_xor_sync(0xffffffffu, p, 1);
        zr[mi] = p;
    }

    if (tx == 0) {
#pragma unroll
        for (int mi = 0; mi < 8; mi++) {
            int r = ty * 8 + mi;
            float z = zr[mi] + b2s;
            float s = 1.f / (1.f + expf(-z));
            if (head < 2) {
                int b = b0u + (r & 7);
                int i = i0 + (r >> 3);
                out[(head ? OFF_RATED : OFF_LIKES) + b * NI + i] = s;
            } else {
                int i = i0 + r;
                if (i < NI) out[OFF_POP + i] = s;
            }
        }
    }
}

// ---------------------------------------------------------------------------
extern "C" void kernel_launch(void* const* d_in, const int* in_sizes, int n_in,
                              void* d_out, int out_size)
{
    const int*   users = (const int*)  d_in[0];
    const float* ue    = (const float*)d_in[1];
    const float* ie    = (const float*)d_in[2];
    const float* lW0 = (const float*)d_in[3];
    const float* lb0 = (const float*)d_in[4];
    const float* lW1 = (const float*)d_in[5];
    const float* lb1 = (const float*)d_in[6];
    const float* lW2 = (const float*)d_in[7];
    const float* lb2 = (const float*)d_in[8];
    const float* rW0 = (const float*)d_in[9];
    const float* rb0 = (const float*)d_in[10];
    const float* rW1 = (const float*)d_in[11];
    const float* rb1 = (const float*)d_in[12];
    const float* rW2 = (const float*)d_in[13];
    const float* rb2 = (const float*)d_in[14];
    const float* pW0 = (const float*)d_in[15];
    const float* pb0 = (const float*)d_in[16];
    const float* pW1 = (const float*)d_in[17];
    const float* pb1 = (const float*)d_in[18];
    const float* pW2 = (const float*)d_in[19];
    const float* pb2 = (const float*)d_in[20];
    float* out = (float*)d_out;

    prep_user<<<3, 256>>>(users, ue, lW0, lb0, rW0, rb0, out + OFF_SIM);
    prep_items<<<(NI + 63) / 64, 256>>>(ie, lW0, rW0, pW0, pb0);
    main_gemm<<<20157, 256>>>(lW1, lb1, lW2, lb2,
                              rW1, rb1, rW2, rb2,
                              pW1, pb1, pW2, pb2,
                              out);
}

// round 3
// speedup vs baseline: 1.2883x; 1.2883x over previous
#include <cuda_runtime.h>
#include <cuda_bf16.h>
#include <math.h>
#include <stdint.h>

// Problem constants
#define NU 100000
#define NI 20000
#define ND 64
#define NH 128
#define NB 64

// Output layout (flattened concat of the returned tuple)
#define OFF_LIKES 0
#define OFF_SIM   1280000
#define OFF_RATED 1284096
#define OFF_POP   2564096

// Scratch (device globals — no allocation allowed)
__device__ float g_au[2][NB * NH];          // per-head: eu@Wu + b0
__device__ float g_C[2][NI * NH];           // per-head: ei@Wi
__device__ float g_Cp[NI * NH];             // popular: relu(ei@pW0 + pb0)
// W1 split into bf16 hi/lo, K-concatenated: rows [0,128)=hi, [128,256)=lo, [256,384)=hi
__device__ __nv_bfloat16 g_Wcat[3][384 * NH];

// ---------------------------------------------------------------------------
// PTX helpers
// ---------------------------------------------------------------------------
__device__ __forceinline__ uint32_t smem_u32(const void* p) {
    return (uint32_t)__cvta_generic_to_shared(p);
}
__device__ __forceinline__ void ldsm_x4(uint32_t* r, uint32_t addr) {
    asm volatile("ldmatrix.sync.aligned.m8n8.x4.shared.b16 {%0,%1,%2,%3}, [%4];"
        : "=r"(r[0]), "=r"(r[1]), "=r"(r[2]), "=r"(r[3]) : "r"(addr));
}
__device__ __forceinline__ void ldsm_x2_trans(uint32_t* r, uint32_t addr) {
    asm volatile("ldmatrix.sync.aligned.m8n8.x2.trans.shared.b16 {%0,%1}, [%2];"
        : "=r"(r[0]), "=r"(r[1]) : "r"(addr));
}
__device__ __forceinline__ void mma_bf16(float* d, const uint32_t* a,
                                         const uint32_t* b, const float* c) {
    asm volatile("mma.sync.aligned.m16n8k16.row.col.f32.bf16.bf16.f32 "
        "{%0,%1,%2,%3}, {%4,%5,%6,%7}, {%8,%9}, {%10,%11,%12,%13};"
        : "=f"(d[0]), "=f"(d[1]), "=f"(d[2]), "=f"(d[3])
        : "r"(a[0]), "r"(a[1]), "r"(a[2]), "r"(a[3]),
          "r"(b[0]), "r"(b[1]),
          "f"(c[0]), "f"(c[1]), "f"(c[2]), "f"(c[3]));
}

// ---------------------------------------------------------------------------
// prep_user: block 0 -> au[likes], block 1 -> au[rated], block 2 -> sim
// ---------------------------------------------------------------------------
__global__ __launch_bounds__(256) void prep_user(
    const int* __restrict__ users, const float* __restrict__ ue,
    const float* __restrict__ lW0, const float* __restrict__ lb0,
    const float* __restrict__ rW0, const float* __restrict__ rb0,
    float* __restrict__ out_sim)
{
    __shared__ float eu_s[NB][ND + 1];
    __shared__ float inv[NB];
    int tid = threadIdx.x;

    for (int idx = tid; idx < NB * ND; idx += 256) {
        int b = idx >> 6, d = idx & 63;
        eu_s[b][d] = ue[users[b] * ND + d];
    }
    __syncthreads();

    int blk = blockIdx.x;
    if (blk < 2) {
        const float* W0 = (blk == 0) ? lW0 : rW0;
        const float* b0 = (blk == 0) ? lb0 : rb0;
        for (int o = tid; o < NB * NH; o += 256) {
            int b = o >> 7, h = o & 127;
            float acc = b0[h];
#pragma unroll
            for (int d = 0; d < ND; d++)
                acc += eu_s[b][d] * W0[d * NH + h];
            g_au[blk][o] = acc;
        }
    } else {
        for (int b = tid; b < NB; b += 256) {
            float s = 0.f;
#pragma unroll
            for (int d = 0; d < ND; d++) { float v = eu_s[b][d]; s += v * v; }
            inv[b] = rsqrtf(fmaxf(s, 1e-12f));
        }
        __syncthreads();
        for (int o = tid; o < NB * NB; o += 256) {
            int a = o >> 6, b = o & 63;
            float s = 0.f;
#pragma unroll
            for (int d = 0; d < ND; d++)
                s += eu_s[a][d] * eu_s[b][d];
            out_sim[o] = -(s * inv[a] * inv[b]);
        }
    }
}

// ---------------------------------------------------------------------------
// prep_items: C_likes = ei@Wi_l, C_rated = ei@Wi_r, C_pop = relu(ei@pW0+pb0)
// ---------------------------------------------------------------------------
__global__ __launch_bounds__(256) void prep_items(
    const float* __restrict__ ie,
    const float* __restrict__ lW0, const float* __restrict__ rW0,
    const float* __restrict__ pW0, const float* __restrict__ pb0)
{
    __shared__ float ei_s[64][ND + 1];
    int tid = threadIdx.x;
    int i0 = blockIdx.x * 64;

    for (int idx = tid; idx < 64 * ND; idx += 256) {
        int ii = idx >> 6, d = idx & 63;
        int i = i0 + ii;
        ei_s[ii][d] = (i < NI) ? ie[i * ND + d] : 0.f;
    }
    __syncthreads();

    for (int o = tid; o < 64 * NH; o += 256) {
        int ii = o >> 7, h = o & 127;
        int i = i0 + ii;
        if (i >= NI) continue;
        float al = 0.f, ar = 0.f, ap = pb0[h];
#pragma unroll
        for (int d = 0; d < ND; d++) {
            float e = ei_s[ii][d];
            al += e * lW0[(ND + d) * NH + h];
            ar += e * rW0[(ND + d) * NH + h];
            ap += e * pW0[d * NH + h];
        }
        g_C[0][i * NH + h] = al;
        g_C[1][i * NH + h] = ar;
        g_Cp[i * NH + h] = fmaxf(ap, 0.f);
    }
}

// ---------------------------------------------------------------------------
// prep_w: split W1 of each head into bf16 hi/lo, K-concatenated [hi; lo; hi]
// ---------------------------------------------------------------------------
__global__ __launch_bounds__(256) void prep_w(
    const float* __restrict__ lW1, const float* __restrict__ rW1,
    const float* __restrict__ pW1)
{
    int idx = blockIdx.x * 256 + threadIdx.x;   // 3 * 128 * 128 = 49152
    if (idx >= 3 * NH * NH) return;
    int h = idx / (NH * NH);
    int rem = idx - h * NH * NH;
    int k = rem >> 7, n = rem & 127;
    const float* W = (h == 0) ? lW1 : (h == 1) ? rW1 : pW1;
    float w = W[k * NH + n];
    __nv_bfloat16 hi = __float2bfloat16(w);
    __nv_bfloat16 lo = __float2bfloat16(w - __bfloat162float(hi));
    g_Wcat[h][k * NH + n] = hi;
    g_Wcat[h][(128 + k) * NH + n] = lo;
    g_Wcat[h][(256 + k) * NH + n] = hi;
}

// ---------------------------------------------------------------------------
// main_mma: fused layer1 (bf16 split tensor-core GEMM, K=384) + layer2 + sigmoid
// Block: 128 rows x 128 cols. 8 warps (2M x 4N), warp tile 64x32, m16n8k16.
// A parts: chunks 0-7 use A_hi (W rows [0,256): hi then lo), chunks 8-11 A_lo.
// ---------------------------------------------------------------------------
__global__ __launch_bounds__(256, 2) void main_mma(
    const float* __restrict__ lb1, const float* __restrict__ lW2, const float* __restrict__ lb2,
    const float* __restrict__ rb1, const float* __restrict__ rW2, const float* __restrict__ rb2,
    const float* __restrict__ pb1, const float* __restrict__ pW2, const float* __restrict__ pb2,
    float* __restrict__ out)
{
    __shared__ __nv_bfloat16 As[128 * 136];   // [row][kpart], stride 136 halves
    __shared__ __nv_bfloat16 Bs[32 * 136];    // [k][n], stride 136
    __shared__ float zpart[4][128];
    __shared__ float b1s[128], w2s[128];
    __shared__ float b2s;

    int tid = threadIdx.x;
    int warp = tid >> 5, lane = tid & 31;
    int warpM = warp >> 2, warpN = warp & 3;
    int m_base = warpM * 64, n_base = warpN * 32;
    int bx = blockIdx.x;

    int head, i0, b0u;
    const float *b1, *W2, *b2;
    if (bx < 20000) {
        head = (bx < 10000) ? 0 : 1;
        int t = bx - head * 10000;
        b0u = (t & 7) * 8;
        i0  = (t >> 3) * 16;
        if (head == 0) { b1 = lb1; W2 = lW2; b2 = lb2; }
        else           { b1 = rb1; W2 = rW2; b2 = rb2; }
    } else {
        head = 2;
        i0 = (bx - 20000) * 128;
        b0u = 0;
        b1 = pb1; W2 = pW2; b2 = pb2;
    }

    if (tid < 128) { b1s[tid] = b1[tid]; w2s[tid] = W2[tid]; }
    if (tid == 0) b2s = b2[0];

    float acc[4][4][4];
#pragma unroll
    for (int f = 0; f < 4; f++)
#pragma unroll
        for (int g2 = 0; g2 < 4; g2++)
#pragma unroll
            for (int q = 0; q < 4; q++) acc[f][g2][q] = 0.f;

    const __nv_bfloat16* Whead = g_Wcat[head];

    for (int c = 0; c < 12; c++) {
        // (Re)build A part: hi at c==0, lo at c==8
        if (c == 0 || c == 8) {
            int part = (c == 8);
            for (int idx = tid; idx < 8192; idx += 256) {
                int r = idx >> 6;
                int kp = idx & 63;
                int k = kp << 1;
                float a0, a1;
                if (head < 2) {
                    int b = b0u + (r & 7);
                    int ii = i0 + (r >> 3);
                    const float* cr = &g_C[head][ii * NH + k];
                    const float* ar = &g_au[head][b * NH + k];
                    a0 = fmaxf(ar[0] + cr[0], 0.f);
                    a1 = fmaxf(ar[1] + cr[1], 0.f);
                } else {
                    int ii = i0 + r;
                    if (ii < NI) {
                        a0 = g_Cp[ii * NH + k];
                        a1 = g_Cp[ii * NH + k + 1];
                    } else { a0 = 0.f; a1 = 0.f; }
                }
                __nv_bfloat16 h0 = __float2bfloat16(a0);
                __nv_bfloat16 h1 = __float2bfloat16(a1);
                if (part) {
                    h0 = __float2bfloat16(a0 - __bfloat162float(h0));
                    h1 = __float2bfloat16(a1 - __bfloat162float(h1));
                }
                uint32_t packed = ((uint32_t)__bfloat16_as_ushort(h1) << 16) |
                                   (uint32_t)__bfloat16_as_ushort(h0);
                *reinterpret_cast<uint32_t*>(&As[r * 136 + k]) = packed;
            }
        }
        // Load W chunk: rows [c*32, c*32+32)
        {
            const __nv_bfloat16* Wsrc = &Whead[(c * 32) * NH];
            for (int idx = tid; idx < 2048; idx += 256) {
                int kk = idx >> 6;
                int np = idx & 63;
                uint32_t v = *reinterpret_cast<const uint32_t*>(&Wsrc[kk * NH + np * 2]);
                *reinterpret_cast<uint32_t*>(&Bs[kk * 136 + np * 2]) = v;
            }
        }
        __syncthreads();

#pragma unroll
        for (int ks = 0; ks < 2; ks++) {
            int kA = ((c & 3) << 5) + (ks << 4);   // A column within current part
            int kB = ks << 4;                      // Bs row
            uint32_t afr[4][4];
#pragma unroll
            for (int f = 0; f < 4; f++) {
                int row = m_base + f * 16 + (lane & 15);
                int col = kA + ((lane >> 4) << 3);
                ldsm_x4(afr[f], smem_u32(&As[row * 136 + col]));
            }
            uint32_t bfr[4][2];
#pragma unroll
            for (int g2 = 0; g2 < 4; g2++) {
                int rowk = kB + (lane & 15);
                int coln = n_base + g2 * 8;
                ldsm_x2_trans(bfr[g2], smem_u32(&Bs[rowk * 136 + coln]));
            }
#pragma unroll
            for (int f = 0; f < 4; f++)
#pragma unroll
                for (int g2 = 0; g2 < 4; g2++)
                    mma_bf16(acc[f][g2], afr[f], bfr[g2], acc[f][g2]);
        }
        __syncthreads();
    }

    // Epilogue: z[row] = sum_n relu(acc + b1[n]) * w2[n]
    int g = lane >> 2, t = lane & 3;
#pragma unroll
    for (int f = 0; f < 4; f++) {
        float z0 = 0.f, z1 = 0.f;
#pragma unroll
        for (int nf = 0; nf < 4; nf++) {
            int col = n_base + nf * 8 + t * 2;
            float b10 = b1s[col], b11 = b1s[col + 1];
            float w0 = w2s[col], w1 = w2s[col + 1];
            z0 += fmaxf(acc[f][nf][0] + b10, 0.f) * w0 + fmaxf(acc[f][nf][1] + b11, 0.f) * w1;
            z1 += fmaxf(acc[f][nf][2] + b10, 0.f) * w0 + fmaxf(acc[f][nf][3] + b11, 0.f) * w1;
        }
        z0 += __shfl_xor_sync(0xffffffffu, z0, 1);
        z0 += __shfl_xor_sync(0xffffffffu, z0, 2);
        z1 += __shfl_xor_sync(0xffffffffu, z1, 1);
        z1 += __shfl_xor_sync(0xffffffffu, z1, 2);
        if (t == 0) {
            zpart[warpN][m_base + f * 16 + g] = z0;
            zpart[warpN][m_base + f * 16 + g + 8] = z1;
        }
    }
    __syncthreads();

    if (tid < 128) {
        float z = zpart[0][tid] + zpart[1][tid] + zpart[2][tid] + zpart[3][tid] + b2s;
        float s = 1.f / (1.f + expf(-z));
        if (head < 2) {
            int b = b0u + (tid & 7);
            int i = i0 + (tid >> 3);
            out[(head ? OFF_RATED : OFF_LIKES) + b * NI + i] = s;
        } else {
            int i = i0 + tid;
            if (i < NI) out[OFF_POP + i] = s;
        }
    }
}

// ---------------------------------------------------------------------------
extern "C" void kernel_launch(void* const* d_in, const int* in_sizes, int n_in,
                              void* d_out, int out_size)
{
    const int*   users = (const int*)  d_in[0];
    const float* ue    = (const float*)d_in[1];
    const float* ie    = (const float*)d_in[2];
    const float* lW0 = (const float*)d_in[3];
    const float* lb0 = (const float*)d_in[4];
    const float* lW1 = (const float*)d_in[5];
    const float* lb1 = (const float*)d_in[6];
    const float* lW2 = (const float*)d_in[7];
    const float* lb2 = (const float*)d_in[8];
    const float* rW0 = (const float*)d_in[9];
    const float* rb0 = (const float*)d_in[10];
    const float* rW1 = (const float*)d_in[11];
    const float* rb1 = (const float*)d_in[12];
    const float* rW2 = (const float*)d_in[13];
    const float* rb2 = (const float*)d_in[14];
    const float* pW0 = (const float*)d_in[15];
    const float* pb0 = (const float*)d_in[16];
    const float* pW1 = (const float*)d_in[17];
    const float* pb1 = (const float*)d_in[18];
    const float* pW2 = (const float*)d_in[19];
    const float* pb2 = (const float*)d_in[20];
    float* out = (float*)d_out;

    prep_user<<<3, 256>>>(users, ue, lW0, lb0, rW0, rb0, out + OFF_SIM);
    prep_items<<<(NI + 63) / 64, 256>>>(ie, lW0, rW0, pW0, pb0);
    prep_w<<<(3 * NH * NH + 255) / 256, 256>>>(lW1, rW1, pW1);
    main_mma<<<20157, 256>>>(lb1, lW2, lb2,
                             rb1, rW2, rb2,
                             pb1, pW2, pb2,
                             out);
}

// round 4
// speedup vs baseline: 2.9311x; 2.2751x over previous
#include <cuda_runtime.h>
#include <cuda_fp16.h>
#include <math.h>
#include <stdint.h>

// Problem constants
#define NU 100000
#define NI 20000
#define ND 64
#define NH 128
#define NB 64

// Output layout (flattened concat of the returned tuple)
#define OFF_LIKES 0
#define OFF_SIM   1280000
#define OFF_RATED 1284096
#define OFF_POP   2564096

// Scratch (device globals — no allocation allowed)
__device__ float g_au[2][NB * NH];     // per-head: eu@Wu + b0
__device__ float g_C[2][NI * NH];      // per-head: ei@Wi
__device__ float g_Cp[NI * NH];        // popular: relu(ei@pW0 + pb0)
__device__ __half g_W16[3][NH * NH];   // W1 per head, fp16, [k][n]

// Dynamic smem layout (halves/floats):
//   As: 128 * 136 half      (34816 B)
//   Bs: 128 * 136 half      (34816 B)
//   zpart: 4 * 128 float    (2048 B)
//   b1s: 128 float, w2s: 128 float, b2s: 1 float
#define SMEM_BYTES (34816 + 34816 + 2048 + 512 + 512 + 16)

// ---------------------------------------------------------------------------
// PTX helpers
// ---------------------------------------------------------------------------
__device__ __forceinline__ uint32_t smem_u32(const void* p) {
    return (uint32_t)__cvta_generic_to_shared(p);
}
__device__ __forceinline__ void ldsm_x4(uint32_t* r, uint32_t addr) {
    asm volatile("ldmatrix.sync.aligned.m8n8.x4.shared.b16 {%0,%1,%2,%3}, [%4];"
        : "=r"(r[0]), "=r"(r[1]), "=r"(r[2]), "=r"(r[3]) : "r"(addr));
}
__device__ __forceinline__ void ldsm_x2_trans(uint32_t* r, uint32_t addr) {
    asm volatile("ldmatrix.sync.aligned.m8n8.x2.trans.shared.b16 {%0,%1}, [%2];"
        : "=r"(r[0]), "=r"(r[1]) : "r"(addr));
}
__device__ __forceinline__ void mma_fp16(float* d, const uint32_t* a,
                                         const uint32_t* b, const float* c) {
    asm volatile("mma.sync.aligned.m16n8k16.row.col.f32.f16.f16.f32 "
        "{%0,%1,%2,%3}, {%4,%5,%6,%7}, {%8,%9}, {%10,%11,%12,%13};"
        : "=f"(d[0]), "=f"(d[1]), "=f"(d[2]), "=f"(d[3])
        : "r"(a[0]), "r"(a[1]), "r"(a[2]), "r"(a[3]),
          "r"(b[0]), "r"(b[1]),
          "f"(c[0]), "f"(c[1]), "f"(c[2]), "f"(c[3]));
}
__device__ __forceinline__ uint32_t pack_h2(float a0, float a1) {
    __half2 h = __floats2half2_rn(a0, a1);
    return *reinterpret_cast<uint32_t*>(&h);
}

// ---------------------------------------------------------------------------
// prep_user: block 0 -> au[likes], block 1 -> au[rated], block 2 -> sim
// ---------------------------------------------------------------------------
__global__ __launch_bounds__(256) void prep_user(
    const int* __restrict__ users, const float* __restrict__ ue,
    const float* __restrict__ lW0, const float* __restrict__ lb0,
    const float* __restrict__ rW0, const float* __restrict__ rb0,
    float* __restrict__ out_sim)
{
    __shared__ float eu_s[NB][ND + 1];
    __shared__ float inv[NB];
    int tid = threadIdx.x;

    for (int idx = tid; idx < NB * ND; idx += 256) {
        int b = idx >> 6, d = idx & 63;
        eu_s[b][d] = ue[users[b] * ND + d];
    }
    __syncthreads();

    int blk = blockIdx.x;
    if (blk < 2) {
        const float* W0 = (blk == 0) ? lW0 : rW0;
        const float* b0 = (blk == 0) ? lb0 : rb0;
        for (int o = tid; o < NB * NH; o += 256) {
            int b = o >> 7, h = o & 127;
            float acc = b0[h];
#pragma unroll
            for (int d = 0; d < ND; d++)
                acc += eu_s[b][d] * W0[d * NH + h];
            g_au[blk][o] = acc;
        }
    } else {
        for (int b = tid; b < NB; b += 256) {
            float s = 0.f;
#pragma unroll
            for (int d = 0; d < ND; d++) { float v = eu_s[b][d]; s += v * v; }
            inv[b] = rsqrtf(fmaxf(s, 1e-12f));
        }
        __syncthreads();
        for (int o = tid; o < NB * NB; o += 256) {
            int a = o >> 6, b = o & 63;
            float s = 0.f;
#pragma unroll
            for (int d = 0; d < ND; d++)
                s += eu_s[a][d] * eu_s[b][d];
            out_sim[o] = -(s * inv[a] * inv[b]);
        }
    }
}

// ---------------------------------------------------------------------------
// prep_items: C_likes = ei@Wi_l, C_rated = ei@Wi_r, C_pop = relu(ei@pW0+pb0)
// ---------------------------------------------------------------------------
__global__ __launch_bounds__(256) void prep_items(
    const float* __restrict__ ie,
    const float* __restrict__ lW0, const float* __restrict__ rW0,
    const float* __restrict__ pW0, const float* __restrict__ pb0)
{
    __shared__ float ei_s[64][ND + 1];
    int tid = threadIdx.x;
    int i0 = blockIdx.x * 64;

    for (int idx = tid; idx < 64 * ND; idx += 256) {
        int ii = idx >> 6, d = idx & 63;
        int i = i0 + ii;
        ei_s[ii][d] = (i < NI) ? ie[i * ND + d] : 0.f;
    }
    __syncthreads();

    for (int o = tid; o < 64 * NH; o += 256) {
        int ii = o >> 7, h = o & 127;
        int i = i0 + ii;
        if (i >= NI) continue;
        float al = 0.f, ar = 0.f, ap = pb0[h];
#pragma unroll
        for (int d = 0; d < ND; d++) {
            float e = ei_s[ii][d];
            al += e * lW0[(ND + d) * NH + h];
            ar += e * rW0[(ND + d) * NH + h];
            ap += e * pW0[d * NH + h];
        }
        g_C[0][i * NH + h] = al;
        g_C[1][i * NH + h] = ar;
        g_Cp[i * NH + h] = fmaxf(ap, 0.f);
    }
}

// ---------------------------------------------------------------------------
// prep_w: convert W1 of each head to fp16 [k][n]
// ---------------------------------------------------------------------------
__global__ __launch_bounds__(256) void prep_w(
    const float* __restrict__ lW1, const float* __restrict__ rW1,
    const float* __restrict__ pW1)
{
    int idx = blockIdx.x * 256 + threadIdx.x;   // 3 * 128 * 128
    if (idx >= 3 * NH * NH) return;
    int h = idx / (NH * NH);
    int rem = idx - h * NH * NH;
    const float* W = (h == 0) ? lW1 : (h == 1) ? rW1 : pW1;
    g_W16[h][rem] = __float2half(W[rem]);
}

// ---------------------------------------------------------------------------
// main_mma: fused layer1 (fp16 tensor-core GEMM, K=128) + layer2 + sigmoid
// Block: 128 rows x 128 cols, 8 warps (2M x 4N), warp tile 64x32, m16n8k16.
// A and full B resident in dynamic smem; single GEMM pass, 8 k-steps.
// ---------------------------------------------------------------------------
__global__ __launch_bounds__(256, 2) void main_mma(
    const float* __restrict__ lb1, const float* __restrict__ lW2, const float* __restrict__ lb2,
    const float* __restrict__ rb1, const float* __restrict__ rW2, const float* __restrict__ rb2,
    const float* __restrict__ pb1, const float* __restrict__ pW2, const float* __restrict__ pb2,
    float* __restrict__ out)
{
    extern __shared__ char dynsmem[];
    __half* As = reinterpret_cast<__half*>(dynsmem);                  // 128 x 136
    __half* Bs = As + 128 * 136;                                      // 128 x 136
    float* zpart = reinterpret_cast<float*>(Bs + 128 * 136);          // [4][128]
    float* b1s = zpart + 4 * 128;
    float* w2s = b1s + 128;
    float* b2sp = w2s + 128;

    int tid = threadIdx.x;
    int warp = tid >> 5, lane = tid & 31;
    int warpM = warp >> 2, warpN = warp & 3;
    int m_base = warpM * 64, n_base = warpN * 32;
    int bx = blockIdx.x;

    int head, i0, b0u;
    const float *b1, *W2, *b2;
    if (bx < 20000) {
        head = (bx < 10000) ? 0 : 1;
        int t = bx - head * 10000;
        b0u = (t & 7) * 8;
        i0  = (t >> 3) * 16;
        if (head == 0) { b1 = lb1; W2 = lW2; b2 = lb2; }
        else           { b1 = rb1; W2 = rW2; b2 = rb2; }
    } else {
        head = 2;
        i0 = (bx - 20000) * 128;
        b0u = 0;
        b1 = pb1; W2 = pW2; b2 = pb2;
    }

    if (tid < 128) { b1s[tid] = b1[tid]; w2s[tid] = W2[tid]; }
    if (tid == 0) b2sp[0] = b2[0];

    // ---- Build A (fp16, relu(au+C) or C_pop), 4 k per thread-iter ----
    for (int idx = tid; idx < 128 * 32; idx += 256) {
        int r = idx >> 5;
        int k = (idx & 31) << 2;
        float4 v;
        if (head < 2) {
            int b = b0u + (r & 7);
            int ii = i0 + (r >> 3);
            float4 cv = *reinterpret_cast<const float4*>(&g_C[head][ii * NH + k]);
            float4 av = *reinterpret_cast<const float4*>(&g_au[head][b * NH + k]);
            v.x = fmaxf(av.x + cv.x, 0.f);
            v.y = fmaxf(av.y + cv.y, 0.f);
            v.z = fmaxf(av.z + cv.z, 0.f);
            v.w = fmaxf(av.w + cv.w, 0.f);
        } else {
            int ii = i0 + r;
            if (ii < NI) v = *reinterpret_cast<const float4*>(&g_Cp[ii * NH + k]);
            else         v = make_float4(0.f, 0.f, 0.f, 0.f);
        }
        uint2 p;
        p.x = pack_h2(v.x, v.y);
        p.y = pack_h2(v.z, v.w);
        *reinterpret_cast<uint2*>(&As[r * 136 + k]) = p;
    }

    // ---- Load full B (fp16 [k][n] -> Bs stride 136) ----
    {
        const __half* Wsrc = g_W16[head];
        for (int idx = tid; idx < 128 * 32; idx += 256) {
            int kk = idx >> 5;
            int n4 = (idx & 31) << 2;
            uint2 v = *reinterpret_cast<const uint2*>(&Wsrc[kk * NH + n4]);
            *reinterpret_cast<uint2*>(&Bs[kk * 136 + n4]) = v;
        }
    }
    __syncthreads();

    // ---- 8 k-steps of m16n8k16 ----
    float acc[4][4][4];
#pragma unroll
    for (int f = 0; f < 4; f++)
#pragma unroll
        for (int g2 = 0; g2 < 4; g2++)
#pragma unroll
            for (int q = 0; q < 4; q++) acc[f][g2][q] = 0.f;

    int arow = lane & 15;
    int acol_off = (lane >> 4) << 3;
    for (int ks = 0; ks < 8; ks++) {
        int kA = (ks << 4) + acol_off;
        uint32_t afr[4][4];
#pragma unroll
        for (int f = 0; f < 4; f++)
            ldsm_x4(afr[f], smem_u32(&As[(m_base + f * 16 + arow) * 136 + kA]));
        uint32_t bfr[4][2];
        int rowk = (ks << 4) + (lane & 15);
#pragma unroll
        for (int g2 = 0; g2 < 4; g2++)
            ldsm_x2_trans(bfr[g2], smem_u32(&Bs[rowk * 136 + n_base + g2 * 8]));
#pragma unroll
        for (int f = 0; f < 4; f++)
#pragma unroll
            for (int g2 = 0; g2 < 4; g2++)
                mma_fp16(acc[f][g2], afr[f], bfr[g2], acc[f][g2]);
    }

    // ---- Epilogue: z[row] = sum_n relu(acc + b1[n]) * w2[n] ----
    int g = lane >> 2, t = lane & 3;
#pragma unroll
    for (int f = 0; f < 4; f++) {
        float z0 = 0.f, z1 = 0.f;
#pragma unroll
        for (int nf = 0; nf < 4; nf++) {
            int col = n_base + nf * 8 + t * 2;
            float b10 = b1s[col], b11 = b1s[col + 1];
            float w0 = w2s[col], w1 = w2s[col + 1];
            z0 += fmaxf(acc[f][nf][0] + b10, 0.f) * w0 + fmaxf(acc[f][nf][1] + b11, 0.f) * w1;
            z1 += fmaxf(acc[f][nf][2] + b10, 0.f) * w0 + fmaxf(acc[f][nf][3] + b11, 0.f) * w1;
        }
        z0 += __shfl_xor_sync(0xffffffffu, z0, 1);
        z0 += __shfl_xor_sync(0xffffffffu, z0, 2);
        z1 += __shfl_xor_sync(0xffffffffu, z1, 1);
        z1 += __shfl_xor_sync(0xffffffffu, z1, 2);
        if (t == 0) {
            zpart[warpN * 128 + m_base + f * 16 + g] = z0;
            zpart[warpN * 128 + m_base + f * 16 + g + 8] = z1;
        }
    }
    __syncthreads();

    if (tid < 128) {
        float z = zpart[tid] + zpart[128 + tid] + zpart[256 + tid] + zpart[384 + tid] + b2sp[0];
        float s = 1.f / (1.f + expf(-z));
        if (head < 2) {
            int b = b0u + (tid & 7);
            int i = i0 + (tid >> 3);
            out[(head ? OFF_RATED : OFF_LIKES) + b * NI + i] = s;
        } else {
            int i = i0 + tid;
            if (i < NI) out[OFF_POP + i] = s;
        }
    }
}

// ---------------------------------------------------------------------------
extern "C" void kernel_launch(void* const* d_in, const int* in_sizes, int n_in,
                              void* d_out, int out_size)
{
    const int*   users = (const int*)  d_in[0];
    const float* ue    = (const float*)d_in[1];
    const float* ie    = (const float*)d_in[2];
    const float* lW0 = (const float*)d_in[3];
    const float* lb0 = (const float*)d_in[4];
    const float* lW1 = (const float*)d_in[5];
    const float* lb1 = (const float*)d_in[6];
    const float* lW2 = (const float*)d_in[7];
    const float* lb2 = (const float*)d_in[8];
    const float* rW0 = (const float*)d_in[9];
    const float* rb0 = (const float*)d_in[10];
    const float* rW1 = (const float*)d_in[11];
    const float* rb1 = (const float*)d_in[12];
    const float* rW2 = (const float*)d_in[13];
    const float* rb2 = (const float*)d_in[14];
    const float* pW0 = (const float*)d_in[15];
    const float* pb0 = (const float*)d_in[16];
    const float* pW1 = (const float*)d_in[17];
    const float* pb1 = (const float*)d_in[18];
    const float* pW2 = (const float*)d_in[19];
    const float* pb2 = (const float*)d_in[20];
    float* out = (float*)d_out;

    cudaFuncSetAttribute(main_mma, cudaFuncAttributeMaxDynamicSharedMemorySize,
                         SMEM_BYTES);

    prep_user<<<3, 256>>>(users, ue, lW0, lb0, rW0, rb0, out + OFF_SIM);
    prep_items<<<(NI + 63) / 64, 256>>>(ie, lW0, rW0, pW0, pb0);
    prep_w<<<(3 * NH * NH + 255) / 256, 256>>>(lW1, rW1, pW1);
    main_mma<<<20157, 256, SMEM_BYTES>>>(lb1, lW2, lb2,
                                         rb1, rW2, rb2,
                                         pb1, pW2, pb2,
                                         out);
}

// round 5
// speedup vs baseline: 4.6616x; 1.5904x over previous
#include <cuda_runtime.h>
#include <cuda_fp16.h>
#include <math.h>
#include <stdint.h>

// Problem constants
#define NU 100000
#define NI 20000
#define ND 64
#define NH 128
#define NB 64

// Output layout (flattened concat of the returned tuple)
#define OFF_LIKES 0
#define OFF_SIM   1280000
#define OFF_RATED 1284096
#define OFF_POP   2564096

#define T_TILES 10
// heads: 2 heads * 8 user-tiles * 125 groups = 2000 blocks
// popular: ceil(157/10) = 16 blocks
#define GRID_MAIN 2016

// Scratch (device globals — no allocation allowed)
__device__ float g_au[2][NB * NH];     // per-head: eu@Wu + b0
__device__ float g_C[2][NI * NH];      // per-head: ei@Wi
__device__ float g_Cp[NI * NH];        // popular: relu(ei@pW0 + pb0)
__device__ __half g_W16[3][NH * NH];   // W1 per head, fp16, [k][n]

// Dynamic smem:
//   As: 2 * 128*136 half  (69632 B)
//   Bs: 128*136 half      (34816 B)
//   zpart: 2*512 float    (4096 B)
//   b1s,w2s: 128+128 float, b2: pad
#define SMEM_BYTES (69632 + 34816 + 4096 + 512 + 512 + 16)

// ---------------------------------------------------------------------------
// PTX helpers
// ---------------------------------------------------------------------------
__device__ __forceinline__ uint32_t smem_u32(const void* p) {
    return (uint32_t)__cvta_generic_to_shared(p);
}
__device__ __forceinline__ void ldsm_x4(uint32_t* r, uint32_t addr) {
    asm volatile("ldmatrix.sync.aligned.m8n8.x4.shared.b16 {%0,%1,%2,%3}, [%4];"
        : "=r"(r[0]), "=r"(r[1]), "=r"(r[2]), "=r"(r[3]) : "r"(addr));
}
__device__ __forceinline__ void ldsm_x2_trans(uint32_t* r, uint32_t addr) {
    asm volatile("ldmatrix.sync.aligned.m8n8.x2.trans.shared.b16 {%0,%1}, [%2];"
        : "=r"(r[0]), "=r"(r[1]) : "r"(addr));
}
__device__ __forceinline__ void mma_fp16(float* d, const uint32_t* a,
                                         const uint32_t* b, const float* c) {
    asm volatile("mma.sync.aligned.m16n8k16.row.col.f32.f16.f16.f32 "
        "{%0,%1,%2,%3}, {%4,%5,%6,%7}, {%8,%9}, {%10,%11,%12,%13};"
        : "=f"(d[0]), "=f"(d[1]), "=f"(d[2]), "=f"(d[3])
        : "r"(a[0]), "r"(a[1]), "r"(a[2]), "r"(a[3]),
          "r"(b[0]), "r"(b[1]),
          "f"(c[0]), "f"(c[1]), "f"(c[2]), "f"(c[3]));
}
__device__ __forceinline__ uint32_t pack_h2(float a0, float a1) {
    __half2 h = __floats2half2_rn(a0, a1);
    return *reinterpret_cast<uint32_t*>(&h);
}

// ---------------------------------------------------------------------------
// prep_all: heterogeneous blocks.
//  bx <  313: items (C_likes, C_rated, C_pop) for 64 items
//  bx == 313/314: au for head 0/1
//  bx == 315: sim
//  bx >= 316: W1 -> fp16 convert (48 blocks x 1024 elems)
// ---------------------------------------------------------------------------
__global__ __launch_bounds__(256) void prep_all(
    const int* __restrict__ users, const float* __restrict__ ue,
    const float* __restrict__ ie,
    const float* __restrict__ lW0, const float* __restrict__ lb0,
    const float* __restrict__ rW0, const float* __restrict__ rb0,
    const float* __restrict__ pW0, const float* __restrict__ pb0,
    const float* __restrict__ lW1, const float* __restrict__ rW1,
    const float* __restrict__ pW1,
    float* __restrict__ out_sim)
{
    int bx = blockIdx.x;
    int tid = threadIdx.x;

    if (bx < 313) {
        __shared__ float ei_s[64][ND + 1];
        int i0 = bx * 64;
        for (int idx = tid; idx < 64 * ND; idx += 256) {
            int ii = idx >> 6, d = idx & 63;
            int i = i0 + ii;
            ei_s[ii][d] = (i < NI) ? ie[i * ND + d] : 0.f;
        }
        __syncthreads();
        for (int o = tid; o < 64 * NH; o += 256) {
            int ii = o >> 7, h = o & 127;
            int i = i0 + ii;
            if (i >= NI) continue;
            float al = 0.f, ar = 0.f, ap = pb0[h];
#pragma unroll
            for (int d = 0; d < ND; d++) {
                float e = ei_s[ii][d];
                al += e * lW0[(ND + d) * NH + h];
                ar += e * rW0[(ND + d) * NH + h];
                ap += e * pW0[d * NH + h];
            }
            g_C[0][i * NH + h] = al;
            g_C[1][i * NH + h] = ar;
            g_Cp[i * NH + h] = fmaxf(ap, 0.f);
        }
    } else if (bx < 316) {
        __shared__ float eu_s[NB][ND + 1];
        __shared__ float inv[NB];
        for (int idx = tid; idx < NB * ND; idx += 256) {
            int b = idx >> 6, d = idx & 63;
            eu_s[b][d] = ue[users[b] * ND + d];
        }
        __syncthreads();
        int blk = bx - 313;
        if (blk < 2) {
            const float* W0 = (blk == 0) ? lW0 : rW0;
            const float* b0 = (blk == 0) ? lb0 : rb0;
            for (int o = tid; o < NB * NH; o += 256) {
                int b = o >> 7, h = o & 127;
                float acc = b0[h];
#pragma unroll
                for (int d = 0; d < ND; d++)
                    acc += eu_s[b][d] * W0[d * NH + h];
                g_au[blk][o] = acc;
            }
        } else {
            for (int b = tid; b < NB; b += 256) {
                float s = 0.f;
#pragma unroll
                for (int d = 0; d < ND; d++) { float v = eu_s[b][d]; s += v * v; }
                inv[b] = rsqrtf(fmaxf(s, 1e-12f));
            }
            __syncthreads();
            for (int o = tid; o < NB * NB; o += 256) {
                int a = o >> 6, b = o & 63;
                float s = 0.f;
#pragma unroll
                for (int d = 0; d < ND; d++)
                    s += eu_s[a][d] * eu_s[b][d];
                out_sim[o] = -(s * inv[a] * inv[b]);
            }
        }
    } else {
        int base = (bx - 316) * 1024 + tid;
#pragma unroll
        for (int j = 0; j < 4; j++) {
            int idx = base + j * 256;
            if (idx < 3 * NH * NH) {
                int h = idx / (NH * NH);
                int rem = idx - h * NH * NH;
                const float* W = (h == 0) ? lW1 : (h == 1) ? rW1 : pW1;
                g_W16[h][rem] = __float2half(W[rem]);
            }
        }
    }
}

// ---------------------------------------------------------------------------
// A-tile builder: 128 rows x 128 k, fp16, into dst (stride 136)
// heads: rows = 8 users x 16 items, A = relu(au + C)
// popular: rows = 128 items, A = C_pop
// ---------------------------------------------------------------------------
__device__ __forceinline__ void build_A(__half* __restrict__ dst, int head,
                                        int b0u, int tt, int tid)
{
    if (head < 2) {
        int i0 = tt * 16;
        for (int idx = tid; idx < 4096; idx += 256) {
            int r = idx >> 5;
            int k = (idx & 31) << 2;
            int b = b0u + (r & 7);
            int ii = i0 + (r >> 3);
            float4 cv = *reinterpret_cast<const float4*>(&g_C[head][ii * NH + k]);
            float4 av = *reinterpret_cast<const float4*>(&g_au[head][b * NH + k]);
            uint2 p;
            p.x = pack_h2(fmaxf(av.x + cv.x, 0.f), fmaxf(av.y + cv.y, 0.f));
            p.y = pack_h2(fmaxf(av.z + cv.z, 0.f), fmaxf(av.w + cv.w, 0.f));
            *reinterpret_cast<uint2*>(&dst[r * 136 + k]) = p;
        }
    } else {
        int i0 = tt * 128;
        for (int idx = tid; idx < 4096; idx += 256) {
            int r = idx >> 5;
            int k = (idx & 31) << 2;
            int ii = i0 + r;
            float4 v = (ii < NI)
                ? *reinterpret_cast<const float4*>(&g_Cp[ii * NH + k])
                : make_float4(0.f, 0.f, 0.f, 0.f);
            uint2 p;
            p.x = pack_h2(v.x, v.y);
            p.y = pack_h2(v.z, v.w);
            *reinterpret_cast<uint2*>(&dst[r * 136 + k]) = p;
        }
    }
}

// ---------------------------------------------------------------------------
// main_mma: multi-tile fused GEMM. Each block: one (head, user-tile), loops
// over T_TILES item tiles. W/b1/w2 resident; A double-buffered; 1 sync/tile.
// ---------------------------------------------------------------------------
__global__ __launch_bounds__(256, 2) void main_mma(
    const float* __restrict__ lb1, const float* __restrict__ lW2, const float* __restrict__ lb2,
    const float* __restrict__ rb1, const float* __restrict__ rW2, const float* __restrict__ rb2,
    const float* __restrict__ pb1, const float* __restrict__ pW2, const float* __restrict__ pb2,
    float* __restrict__ out)
{
    extern __shared__ char dynsmem[];
    __half* As = reinterpret_cast<__half*>(dynsmem);          // 2 x (128*136)
    __half* Bs = As + 2 * 128 * 136;                          // 128*136
    float* zpart = reinterpret_cast<float*>(Bs + 128 * 136);  // 2 x 512
    float* b1s = zpart + 1024;
    float* w2s = b1s + 128;
    float* b2sp = w2s + 128;

    int tid = threadIdx.x;
    int warp = tid >> 5, lane = tid & 31;
    int warpM = warp >> 2, warpN = warp & 3;
    int m_base = warpM * 64, n_base = warpN * 32;
    int bx = blockIdx.x;

    int head, b0u = 0, t0, nt;
    const float *b1, *W2, *b2;
    if (bx < 2000) {
        head = bx / 1000;
        int rem = bx - head * 1000;
        b0u = (rem / 125) * 8;
        t0 = (rem % 125) * T_TILES;
        nt = T_TILES;
        if (head == 0) { b1 = lb1; W2 = lW2; b2 = lb2; }
        else           { b1 = rb1; W2 = rW2; b2 = rb2; }
    } else {
        head = 2;
        t0 = (bx - 2000) * T_TILES;
        nt = min(T_TILES, 157 - t0);
        b1 = pb1; W2 = pW2; b2 = pb2;
    }

    if (tid < 128) { b1s[tid] = b1[tid]; w2s[tid] = W2[tid]; }
    if (tid == 0) b2sp[0] = b2[0];

    // Load full B once (fp16 [k][n] -> Bs stride 136)
    {
        const __half* Wsrc = g_W16[head];
        for (int idx = tid; idx < 4096; idx += 256) {
            int kk = idx >> 5;
            int n4 = (idx & 31) << 2;
            uint2 v = *reinterpret_cast<const uint2*>(&Wsrc[kk * NH + n4]);
            *reinterpret_cast<uint2*>(&Bs[kk * 136 + n4]) = v;
        }
    }
    // Build first A tile into buffer 0
    build_A(As, head, b0u, t0, tid);
    __syncthreads();

    int arow = lane & 15;
    int acol_off = (lane >> 4) << 3;
    int g = lane >> 2, tq = lane & 3;

    int p = 0;
    for (int t = 0; t < nt; t++) {
        int tt = t0 + t;
        const __half* Ab = As + p * (128 * 136);

        float acc[4][4][4];
#pragma unroll
        for (int f = 0; f < 4; f++)
#pragma unroll
            for (int g2 = 0; g2 < 4; g2++)
#pragma unroll
                for (int q = 0; q < 4; q++) acc[f][g2][q] = 0.f;

        // ---- 8 k-steps of m16n8k16 ----
#pragma unroll
        for (int ks = 0; ks < 8; ks++) {
            int kA = (ks << 4) + acol_off;
            uint32_t afr[4][4];
#pragma unroll
            for (int f = 0; f < 4; f++)
                ldsm_x4(afr[f], smem_u32(&Ab[(m_base + f * 16 + arow) * 136 + kA]));
            uint32_t bfr[4][2];
            int rowk = (ks << 4) + (lane & 15);
#pragma unroll
            for (int g2 = 0; g2 < 4; g2++)
                ldsm_x2_trans(bfr[g2], smem_u32(&Bs[rowk * 136 + n_base + g2 * 8]));
#pragma unroll
            for (int f = 0; f < 4; f++)
#pragma unroll
                for (int g2 = 0; g2 < 4; g2++)
                    mma_fp16(acc[f][g2], afr[f], bfr[g2], acc[f][g2]);
        }

        // ---- Prefetch-build next A tile into other buffer ----
        if (t + 1 < nt)
            build_A(As + (p ^ 1) * (128 * 136), head, b0u, tt + 1, tid);

        // ---- Epilogue partials ----
        float* zp = zpart + p * 512;
#pragma unroll
        for (int f = 0; f < 4; f++) {
            float z0 = 0.f, z1 = 0.f;
#pragma unroll
            for (int nf = 0; nf < 4; nf++) {
                int col = n_base + nf * 8 + tq * 2;
                float b10 = b1s[col], b11 = b1s[col + 1];
                float w0 = w2s[col], w1 = w2s[col + 1];
                z0 += fmaxf(acc[f][nf][0] + b10, 0.f) * w0 + fmaxf(acc[f][nf][1] + b11, 0.f) * w1;
                z1 += fmaxf(acc[f][nf][2] + b10, 0.f) * w0 + fmaxf(acc[f][nf][3] + b11, 0.f) * w1;
            }
            z0 += __shfl_xor_sync(0xffffffffu, z0, 1);
            z0 += __shfl_xor_sync(0xffffffffu, z0, 2);
            z1 += __shfl_xor_sync(0xffffffffu, z1, 1);
            z1 += __shfl_xor_sync(0xffffffffu, z1, 2);
            if (tq == 0) {
                zp[warpN * 128 + m_base + f * 16 + g] = z0;
                zp[warpN * 128 + m_base + f * 16 + g + 8] = z1;
            }
        }
        __syncthreads();   // zpart ready + next A ready

        if (tid < 128) {
            float z = zp[tid] + zp[128 + tid] + zp[256 + tid] + zp[384 + tid] + b2sp[0];
            float s = 1.f / (1.f + expf(-z));
            if (head < 2) {
                int b = b0u + (tid & 7);
                int i = tt * 16 + (tid >> 3);
                out[(head ? OFF_RATED : OFF_LIKES) + b * NI + i] = s;
            } else {
                int i = tt * 128 + tid;
                if (i < NI) out[OFF_POP + i] = s;
            }
        }
        p ^= 1;
    }
}

// ---------------------------------------------------------------------------
extern "C" void kernel_launch(void* const* d_in, const int* in_sizes, int n_in,
                              void* d_out, int out_size)
{
    const int*   users = (const int*)  d_in[0];
    const float* ue    = (const float*)d_in[1];
    const float* ie    = (const float*)d_in[2];
    const float* lW0 = (const float*)d_in[3];
    const float* lb0 = (const float*)d_in[4];
    const float* lW1 = (const float*)d_in[5];
    const float* lb1 = (const float*)d_in[6];
    const float* lW2 = (const float*)d_in[7];
    const float* lb2 = (const float*)d_in[8];
    const float* rW0 = (const float*)d_in[9];
    const float* rb0 = (const float*)d_in[10];
    const float* rW1 = (const float*)d_in[11];
    const float* rb1 = (const float*)d_in[12];
    const float* rW2 = (const float*)d_in[13];
    const float* rb2 = (const float*)d_in[14];
    const float* pW0 = (const float*)d_in[15];
    const float* pb0 = (const float*)d_in[16];
    const float* pW1 = (const float*)d_in[17];
    const float* pb1 = (const float*)d_in[18];
    const float* pW2 = (const float*)d_in[19];
    const float* pb2 = (const float*)d_in[20];
    float* out = (float*)d_out;

    cudaFuncSetAttribute(main_mma, cudaFuncAttributeMaxDynamicSharedMemorySize,
                         SMEM_BYTES);

    prep_all<<<364, 256>>>(users, ue, ie,
                           lW0, lb0, rW0, rb0, pW0, pb0,
                           lW1, rW1, pW1,
                           out + OFF_SIM);
    main_mma<<<GRID_MAIN, 256, SMEM_BYTES>>>(lb1, lW2, lb2,
                                             rb1, rW2, rb2,
                                             pb1, pW2, pb2,
                                             out);
}

// round 8
// speedup vs baseline: 4.7827x; 1.0260x over previous
#include <cuda_runtime.h>
#include <cuda_fp16.h>
#include <math.h>
#include <stdint.h>

// Problem constants
#define NU 100000
#define NI 20000
#define ND 64
#define NH 128
#define NB 64

// Output layout (flattened concat of the returned tuple)
#define OFF_LIKES 0
#define OFF_SIM   1280000
#define OFF_RATED 1284096
#define OFF_POP   2564096

#define T_TILES 10
// heads: 2 heads * 8 user-tiles * 125 groups = 2000 blocks; popular: 16 blocks
#define GRID_MAIN 2016

// Scratch (device globals — no allocation allowed)
__device__ __half g_au16[2][NB * NH];   // per-head: fp16(eu@Wu + b0)
__device__ __half g_C16[2][NI * NH];    // per-head: fp16(ei@Wi)
__device__ __half g_Cp16[NI * NH];      // popular: fp16(relu(ei@pW0 + pb0))
__device__ __half g_W16[3][NH * NH];    // W1 per head, fp16, [k][n]

// Dynamic smem:
//   As: 2 * 128*136 half  (69632 B)
//   Bs: 128*136 half      (34816 B)
//   zpart: 2*512 float    (4096 B)
//   b1s,w2s: 128+128 float, b2 pad
#define SMEM_BYTES (69632 + 34816 + 4096 + 512 + 512 + 16)

// ---------------------------------------------------------------------------
// PTX helpers
// ---------------------------------------------------------------------------
__device__ __forceinline__ uint32_t smem_u32(const void* p) {
    return (uint32_t)__cvta_generic_to_shared(p);
}
__device__ __forceinline__ void ldsm_x4(uint32_t* r, uint32_t addr) {
    asm volatile("ldmatrix.sync.aligned.m8n8.x4.shared.b16 {%0,%1,%2,%3}, [%4];"
        : "=r"(r[0]), "=r"(r[1]), "=r"(r[2]), "=r"(r[3]) : "r"(addr));
}
__device__ __forceinline__ void ldsm_x2_trans(uint32_t* r, uint32_t addr) {
    asm volatile("ldmatrix.sync.aligned.m8n8.x2.trans.shared.b16 {%0,%1}, [%2];"
        : "=r"(r[0]), "=r"(r[1]) : "r"(addr));
}
__device__ __forceinline__ void mma_fp16(float* d, const uint32_t* a,
                                         const uint32_t* b, const float* c) {
    asm volatile("mma.sync.aligned.m16n8k16.row.col.f32.f16.f16.f32 "
        "{%0,%1,%2,%3}, {%4,%5,%6,%7}, {%8,%9}, {%10,%11,%12,%13};"
        : "=f"(d[0]), "=f"(d[1]), "=f"(d[2]), "=f"(d[3])
        : "r"(a[0]), "r"(a[1]), "r"(a[2]), "r"(a[3]),
          "r"(b[0]), "r"(b[1]),
          "f"(c[0]), "f"(c[1]), "f"(c[2]), "f"(c[3]));
}

// ---------------------------------------------------------------------------
// prep_all: heterogeneous blocks.
//  bx <  939: per-head item staging (3 heads x 313 blocks of 64 items)
//  bx == 939/940: au for head 0/1 (fp16)
//  bx == 941: sim
//  bx >= 942: W1 -> fp16 convert (48 blocks)
// ---------------------------------------------------------------------------
__global__ __launch_bounds__(256) void prep_all(
    const int* __restrict__ users, const float* __restrict__ ue,
    const float* __restrict__ ie,
    const float* __restrict__ lW0, const float* __restrict__ lb0,
    const float* __restrict__ rW0, const float* __restrict__ rb0,
    const float* __restrict__ pW0, const float* __restrict__ pb0,
    const float* __restrict__ lW1, const float* __restrict__ rW1,
    const float* __restrict__ pW1,
    float* __restrict__ out_sim)
{
    int bx = blockIdx.x;
    int tid = threadIdx.x;

    if (bx < 939) {
        int h = bx / 313;
        int blk = bx - h * 313;
        __shared__ float ei_s[64][ND + 1];
        int i0 = blk * 64;
        for (int idx = tid; idx < 64 * ND; idx += 256) {
            int ii = idx >> 6, d = idx & 63;
            int i = i0 + ii;
            ei_s[ii][d] = (i < NI) ? ie[i * ND + d] : 0.f;
        }
        __syncthreads();
        if (h < 2) {
            const float* W0 = (h == 0) ? lW0 : rW0;
            for (int o = tid; o < 64 * NH; o += 256) {
                int ii = o >> 7, hh = o & 127;
                int i = i0 + ii;
                if (i >= NI) continue;
                float a = 0.f;
#pragma unroll
                for (int d = 0; d < ND; d++)
                    a += ei_s[ii][d] * W0[(ND + d) * NH + hh];
                g_C16[h][i * NH + hh] = __float2half(a);
            }
        } else {
            for (int o = tid; o < 64 * NH; o += 256) {
                int ii = o >> 7, hh = o & 127;
                int i = i0 + ii;
                if (i >= NI) continue;
                float a = pb0[hh];
#pragma unroll
                for (int d = 0; d < ND; d++)
                    a += ei_s[ii][d] * pW0[d * NH + hh];
                g_Cp16[i * NH + hh] = __float2half(fmaxf(a, 0.f));
            }
        }
    } else if (bx < 942) {
        __shared__ float eu_s[NB][ND + 1];
        __shared__ float inv[NB];
        for (int idx = tid; idx < NB * ND; idx += 256) {
            int b = idx >> 6, d = idx & 63;
            eu_s[b][d] = ue[users[b] * ND + d];
        }
        __syncthreads();
        int blk = bx - 939;
        if (blk < 2) {
            const float* W0 = (blk == 0) ? lW0 : rW0;
            const float* b0 = (blk == 0) ? lb0 : rb0;
            for (int o = tid; o < NB * NH; o += 256) {
                int b = o >> 7, h = o & 127;
                float acc = b0[h];
#pragma unroll
                for (int d = 0; d < ND; d++)
                    acc += eu_s[b][d] * W0[d * NH + h];
                g_au16[blk][o] = __float2half(acc);
            }
        } else {
            for (int b = tid; b < NB; b += 256) {
                float s = 0.f;
#pragma unroll
                for (int d = 0; d < ND; d++) { float v = eu_s[b][d]; s += v * v; }
                inv[b] = rsqrtf(fmaxf(s, 1e-12f));
            }
            __syncthreads();
            for (int o = tid; o < NB * NB; o += 256) {
                int a = o >> 6, b = o & 63;
                float s = 0.f;
#pragma unroll
                for (int d = 0; d < ND; d++)
                    s += eu_s[a][d] * eu_s[b][d];
                out_sim[o] = -(s * inv[a] * inv[b]);
            }
        }
    } else {
        int base = (bx - 942) * 1024 + tid;
#pragma unroll
        for (int j = 0; j < 4; j++) {
            int idx = base + j * 256;
            if (idx < 3 * NH * NH) {
                int h = idx / (NH * NH);
                int rem = idx - h * NH * NH;
                const float* W = (h == 0) ? lW1 : (h == 1) ? rW1 : pW1;
                g_W16[h][rem] = __float2half(W[rem]);
            }
        }
    }
}

// ---------------------------------------------------------------------------
// A-tile builder (fp16 in, fp16 out): 128 rows x 128 k into As (stride 136)
// heads: rows = 8 users x 16 items, A = relu(au16 + C16); popular: C_pop16
// ---------------------------------------------------------------------------
__device__ __forceinline__ void build_A(__half* __restrict__ dst, int head,
                                        int b0u, int tt, int tid)
{
    const __half2 z2 = __floats2half2_rn(0.f, 0.f);
    if (head < 2) {
        int i0 = tt * 16;
        for (int idx = tid; idx < 4096; idx += 256) {
            int r = idx >> 5;
            int k = (idx & 31) << 2;
            int b = b0u + (r & 7);
            int ii = i0 + (r >> 3);
            uint2 cv = *reinterpret_cast<const uint2*>(&g_C16[head][ii * NH + k]);
            uint2 av = *reinterpret_cast<const uint2*>(&g_au16[head][b * NH + k]);
            __half2 s0 = __hmax2(__hadd2(*reinterpret_cast<__half2*>(&cv.x),
                                         *reinterpret_cast<__half2*>(&av.x)), z2);
            __half2 s1 = __hmax2(__hadd2(*reinterpret_cast<__half2*>(&cv.y),
                                         *reinterpret_cast<__half2*>(&av.y)), z2);
            uint2 p;
            p.x = *reinterpret_cast<uint32_t*>(&s0);
            p.y = *reinterpret_cast<uint32_t*>(&s1);
            *reinterpret_cast<uint2*>(&dst[r * 136 + k]) = p;
        }
    } else {
        int i0 = tt * 128;
        for (int idx = tid; idx < 4096; idx += 256) {
            int r = idx >> 5;
            int k = (idx & 31) << 2;
            int ii = i0 + r;
            uint2 p = (ii < NI)
                ? *reinterpret_cast<const uint2*>(&g_Cp16[ii * NH + k])
                : make_uint2(0u, 0u);
            *reinterpret_cast<uint2*>(&dst[r * 136 + k]) = p;
        }
    }
}

// ---------------------------------------------------------------------------
// main_mma: multi-tile fused GEMM. Each block: one (head, user-tile), loops
// over T_TILES item tiles. B/params resident; A double-buffered; 1 sync/tile.
// ---------------------------------------------------------------------------
__global__ __launch_bounds__(256, 2) void main_mma(
    const float* __restrict__ lb1, const float* __restrict__ lW2, const float* __restrict__ lb2,
    const float* __restrict__ rb1, const float* __restrict__ rW2, const float* __restrict__ rb2,
    const float* __restrict__ pb1, const float* __restrict__ pW2, const float* __restrict__ pb2,
    float* __restrict__ out)
{
    extern __shared__ char dynsmem[];
    __half* As = reinterpret_cast<__half*>(dynsmem);          // 2 x (128*136)
    __half* Bs = As + 2 * 128 * 136;                          // 128*136
    float* zpart = reinterpret_cast<float*>(Bs + 128 * 136);  // 2 x 512
    float* b1s = zpart + 1024;
    float* w2s = b1s + 128;
    float* b2sp = w2s + 128;

    int tid = threadIdx.x;
    int warp = tid >> 5, lane = tid & 31;
    int warpM = warp >> 2, warpN = warp & 3;
    int m_base = warpM * 64, n_base = warpN * 32;
    int bx = blockIdx.x;

    int head, b0u = 0, t0, nt;
    const float *b1, *W2, *b2;
    if (bx < 2000) {
        head = bx / 1000;
        int rem = bx - head * 1000;
        b0u = (rem / 125) * 8;
        t0 = (rem % 125) * T_TILES;
        nt = T_TILES;
        if (head == 0) { b1 = lb1; W2 = lW2; b2 = lb2; }
        else           { b1 = rb1; W2 = rW2; b2 = rb2; }
    } else {
        head = 2;
        t0 = (bx - 2000) * T_TILES;
        nt = min(T_TILES, 157 - t0);
        b1 = pb1; W2 = pW2; b2 = pb2;
    }

    if (tid < 128) { b1s[tid] = b1[tid]; w2s[tid] = W2[tid]; }
    if (tid == 0) b2sp[0] = b2[0];

    // Load full B once (fp16 [k][n] -> Bs stride 136)
    {
        const __half* Wsrc = g_W16[head];
        for (int idx = tid; idx < 4096; idx += 256) {
            int kk = idx >> 5;
            int n4 = (idx & 31) << 2;
            uint2 v = *reinterpret_cast<const uint2*>(&Wsrc[kk * NH + n4]);
            *reinterpret_cast<uint2*>(&Bs[kk * 136 + n4]) = v;
        }
    }
    // Build first A tile into buffer 0
    build_A(As, head, b0u, t0, tid);
    __syncthreads();

    int arow = lane & 15;
    int acol_off = (lane >> 4) << 3;
    int g = lane >> 2, tq = lane & 3;

    int p = 0;
    for (int t = 0; t < nt; t++) {
        int tt = t0 + t;
        const __half* Ab = As + p * (128 * 136);

        float acc[4][4][4];
#pragma unroll
        for (int f = 0; f < 4; f++)
#pragma unroll
            for (int g2 = 0; g2 < 4; g2++)
#pragma unroll
                for (int q = 0; q < 4; q++) acc[f][g2][q] = 0.f;

        // ---- 8 k-steps of m16n8k16 ----
#pragma unroll
        for (int ks = 0; ks < 8; ks++) {
            int kA = (ks << 4) + acol_off;
            uint32_t afr[4][4];
#pragma unroll
            for (int f = 0; f < 4; f++)
                ldsm_x4(afr[f], smem_u32(&Ab[(m_base + f * 16 + arow) * 136 + kA]));
            uint32_t bfr[4][2];
            int rowk = (ks << 4) + (lane & 15);
#pragma unroll
            for (int g2 = 0; g2 < 4; g2++)
                ldsm_x2_trans(bfr[g2], smem_u32(&Bs[rowk * 136 + n_base + g2 * 8]));
#pragma unroll
            for (int f = 0; f < 4; f++)
#pragma unroll
                for (int g2 = 0; g2 < 4; g2++)
                    mma_fp16(acc[f][g2], afr[f], bfr[g2], acc[f][g2]);
        }

        // ---- Prefetch-build next A tile into other buffer ----
        if (t + 1 < nt)
            build_A(As + (p ^ 1) * (128 * 136), head, b0u, tt + 1, tid);

        // ---- Epilogue partials ----
        float* zp = zpart + p * 512;
#pragma unroll
        for (int f = 0; f < 4; f++) {
            float z0 = 0.f, z1 = 0.f;
#pragma unroll
            for (int nf = 0; nf < 4; nf++) {
                int col = n_base + nf * 8 + tq * 2;
                float b10 = b1s[col], b11 = b1s[col + 1];
                float w0 = w2s[col], w1 = w2s[col + 1];
                z0 += fmaxf(acc[f][nf][0] + b10, 0.f) * w0 + fmaxf(acc[f][nf][1] + b11, 0.f) * w1;
                z1 += fmaxf(acc[f][nf][2] + b10, 0.f) * w0 + fmaxf(acc[f][nf][3] + b11, 0.f) * w1;
            }
            z0 += __shfl_xor_sync(0xffffffffu, z0, 1);
            z0 += __shfl_xor_sync(0xffffffffu, z0, 2);
            z1 += __shfl_xor_sync(0xffffffffu, z1, 1);
            z1 += __shfl_xor_sync(0xffffffffu, z1, 2);
            if (tq == 0) {
                zp[warpN * 128 + m_base + f * 16 + g] = z0;
                zp[warpN * 128 + m_base + f * 16 + g + 8] = z1;
            }
        }
        __syncthreads();   // zpart ready + next A ready

        if (tid < 128) {
            if (head < 2) {
                // coalesced: 16 consecutive tids -> 16 consecutive items of one user
                int r = ((tid & 15) << 3) | (tid >> 4);
                float z = zp[r] + zp[128 + r] + zp[256 + r] + zp[384 + r] + b2sp[0];
                float s = 1.f / (1.f + __expf(-z));
                int b = b0u + (tid >> 4);
                int i = tt * 16 + (tid & 15);
                out[(head ? OFF_RATED : OFF_LIKES) + b * NI + i] = s;
            } else {
                float z = zp[tid] + zp[128 + tid] + zp[256 + tid] + zp[384 + tid] + b2sp[0];
                float s = 1.f / (1.f + __expf(-z));
                int i = tt * 128 + tid;
                if (i < NI) out[OFF_POP + i] = s;
            }
        }
        p ^= 1;
    }
}

// ---------------------------------------------------------------------------
extern "C" void kernel_launch(void* const* d_in, const int* in_sizes, int n_in,
                              void* d_out, int out_size)
{
    const int*   users = (const int*)  d_in[0];
    const float* ue    = (const float*)d_in[1];
    const float* ie    = (const float*)d_in[2];
    const float* lW0 = (const float*)d_in[3];
    const float* lb0 = (const float*)d_in[4];
    const float* lW1 = (const float*)d_in[5];
    const float* lb1 = (const float*)d_in[6];
    const float* lW2 = (const float*)d_in[7];
    const float* lb2 = (const float*)d_in[8];
    const float* rW0 = (const float*)d_in[9];
    const float* rb0 = (const float*)d_in[10];
    const float* rW1 = (const float*)d_in[11];
    const float* rb1 = (const float*)d_in[12];
    const float* rW2 = (const float*)d_in[13];
    const float* rb2 = (const float*)d_in[14];
    const float* pW0 = (const float*)d_in[15];
    const float* pb0 = (const float*)d_in[16];
    const float* pW1 = (const float*)d_in[17];
    const float* pb1 = (const float*)d_in[18];
    const float* pW2 = (const float*)d_in[19];
    const float* pb2 = (const float*)d_in[20];
    float* out = (float*)d_out;

    cudaFuncSetAttribute(main_mma, cudaFuncAttributeMaxDynamicSharedMemorySize,
                         SMEM_BYTES);

    prep_all<<<990, 256>>>(users, ue, ie,
                           lW0, lb0, rW0, rb0, pW0, pb0,
                           lW1, rW1, pW1,
                           out + OFF_SIM);
    main_mma<<<GRID_MAIN, 256, SMEM_BYTES>>>(lb1, lW2, lb2,
                                             rb1, rW2, rb2,
                                             pb1, pW2, pb2,
                                             out);
}

// round 10
// speedup vs baseline: 5.8614x; 1.2255x over previous
#include <cuda_runtime.h>
#include <cuda_fp16.h>
#include <math.h>
#include <stdint.h>

// Problem constants
#define NU 100000
#define NI 20000
#define ND 64
#define NH 128
#define NB 64

// Output layout (flattened concat of the returned tuple)
#define OFF_LIKES 0
#define OFF_SIM   1280000
#define OFF_RATED 1284096
#define OFF_POP   2564096

#define T_TILES 10
// heads: 2 heads * 8 user-tiles * 125 groups = 2000 blocks; popular: 16 blocks
#define GRID_MAIN 2016

// Scratch (device globals — no allocation allowed)
__device__ __half g_au16[2][NB * NH];   // per-head: fp16(eu@Wu + b0)
__device__ __half g_C16[2][NI * NH];    // per-head: fp16(ei@Wi)
__device__ __half g_Cp16[NI * NH];      // popular: fp16(relu(ei@pW0 + pb0))
__device__ __half g_W16[3][NH * NH];    // W1 per head, fp16, [k][n]

// Dynamic smem (main_mma):
//   As: 2 * 128*136 half  (69632 B)
//   Bs: 128*136 half      (34816 B)
//   zpart: 2*512 float    (4096 B)
//   b1s,w2s: 128+128 float, b2 pad
#define SMEM_BYTES (69632 + 34816 + 4096 + 512 + 512 + 16)

// ---------------------------------------------------------------------------
// PTX helpers
// ---------------------------------------------------------------------------
__device__ __forceinline__ uint32_t smem_u32(const void* p) {
    return (uint32_t)__cvta_generic_to_shared(p);
}
__device__ __forceinline__ void ldsm_x4(uint32_t* r, uint32_t addr) {
    asm volatile("ldmatrix.sync.aligned.m8n8.x4.shared.b16 {%0,%1,%2,%3}, [%4];"
        : "=r"(r[0]), "=r"(r[1]), "=r"(r[2]), "=r"(r[3]) : "r"(addr));
}
__device__ __forceinline__ void ldsm_x4_trans(uint32_t* r, uint32_t addr) {
    asm volatile("ldmatrix.sync.aligned.m8n8.x4.trans.shared.b16 {%0,%1,%2,%3}, [%4];"
        : "=r"(r[0]), "=r"(r[1]), "=r"(r[2]), "=r"(r[3]) : "r"(addr));
}
__device__ __forceinline__ void mma_fp16(float* d, const uint32_t* a,
                                         const uint32_t* b, const float* c) {
    asm volatile("mma.sync.aligned.m16n8k16.row.col.f32.f16.f16.f32 "
        "{%0,%1,%2,%3}, {%4,%5,%6,%7}, {%8,%9}, {%10,%11,%12,%13};"
        : "=f"(d[0]), "=f"(d[1]), "=f"(d[2]), "=f"(d[3])
        : "r"(a[0]), "r"(a[1]), "r"(a[2]), "r"(a[3]),
          "r"(b[0]), "r"(b[1]),
          "f"(c[0]), "f"(c[1]), "f"(c[2]), "f"(c[3]));
}

// ---------------------------------------------------------------------------
// prep_all: heterogeneous blocks.
//  bx <  939: per-head item staging (3 heads x 313 blocks of 64 items),
//             register-blocked GEMM: thread computes 4 items x 8 h.
//  bx == 939/940: au for head 0/1 (fp16)
//  bx == 941: sim
//  bx >= 942: W1 -> fp16 convert (48 blocks)
// ---------------------------------------------------------------------------
__global__ __launch_bounds__(256) void prep_all(
    const int* __restrict__ users, const float* __restrict__ ue,
    const float* __restrict__ ie,
    const float* __restrict__ lW0, const float* __restrict__ lb0,
    const float* __restrict__ rW0, const float* __restrict__ rb0,
    const float* __restrict__ pW0, const float* __restrict__ pb0,
    const float* __restrict__ lW1, const float* __restrict__ rW1,
    const float* __restrict__ pW1,
    float* __restrict__ out_sim)
{
    __shared__ __align__(16) char pbuf[33024];
    int bx = blockIdx.x;
    int tid = threadIdx.x;

    if (bx < 939) {
        int h = bx / 313;
        int blk = bx - h * 313;
        float (*eiN)[65]  = reinterpret_cast<float(*)[65]>(pbuf);          // 64x65
        float (*w0s)[128] = reinterpret_cast<float(*)[128]>(pbuf + 16640); // 32x128
        int i0 = blk * 64;
        int tx = tid & 15, ty = tid >> 4;     // tx: h-group (8 h), ty: item-group (4 items)

        // Coalesced load of ei tile [64 items][64 d]
        for (int idx = tid; idx < 4096; idx += 256) {
            int it = idx >> 6, d = idx & 63;
            int i = i0 + it;
            eiN[it][d] = (i < NI) ? ie[i * ND + d] : 0.f;
        }

        const float* W0 = (h == 0) ? lW0 : (h == 1) ? rW0 : pW0;
        int roff = (h < 2) ? ND : 0;   // heads use Wi = rows [64,128); popular rows [0,64)

        float acc[4][8];
#pragma unroll
        for (int i = 0; i < 4; i++)
#pragma unroll
            for (int j = 0; j < 8; j++) acc[i][j] = 0.f;

        for (int ch = 0; ch < 2; ch++) {
            __syncthreads();   // eiN ready (ch=0) / previous chunk consumed (ch=1)
            // Load W0 chunk: 32 rows x 128 cols, float4-coalesced
            for (int idx = tid; idx < 1024; idx += 256) {
                int d = idx >> 5, c4 = (idx & 31) << 2;
                *reinterpret_cast<float4*>(&w0s[d][c4]) =
                    *reinterpret_cast<const float4*>(&W0[(roff + ch * 32 + d) * NH + c4]);
            }
            __syncthreads();
#pragma unroll 8
            for (int d = 0; d < 32; d++) {
                int dd = ch * 32 + d;
                float e0 = eiN[ty * 4 + 0][dd];
                float e1 = eiN[ty * 4 + 1][dd];
                float e2 = eiN[ty * 4 + 2][dd];
                float e3 = eiN[ty * 4 + 3][dd];
                float4 wa = *reinterpret_cast<float4*>(&w0s[d][tx * 8]);
                float4 wb = *reinterpret_cast<float4*>(&w0s[d][tx * 8 + 4]);
                float w[8] = {wa.x, wa.y, wa.z, wa.w, wb.x, wb.y, wb.z, wb.w};
#pragma unroll
                for (int j = 0; j < 8; j++) {
                    acc[0][j] += e0 * w[j];
                    acc[1][j] += e1 * w[j];
                    acc[2][j] += e2 * w[j];
                    acc[3][j] += e3 * w[j];
                }
            }
        }

        // Write fp16 outputs: 8 consecutive h per item -> uint4 store
        int hbase = tx * 8;
#pragma unroll
        for (int i = 0; i < 4; i++) {
            int item = i0 + ty * 4 + i;
            if (item >= NI) continue;
            float v[8];
#pragma unroll
            for (int j = 0; j < 8; j++) {
                float a = acc[i][j];
                if (h == 2) a = fmaxf(a + pb0[hbase + j], 0.f);
                v[j] = a;
            }
            __half2 h0 = __floats2half2_rn(v[0], v[1]);
            __half2 h1 = __floats2half2_rn(v[2], v[3]);
            __half2 h2 = __floats2half2_rn(v[4], v[5]);
            __half2 h3 = __floats2half2_rn(v[6], v[7]);
            uint4 pk;
            pk.x = *reinterpret_cast<uint32_t*>(&h0);
            pk.y = *reinterpret_cast<uint32_t*>(&h1);
            pk.z = *reinterpret_cast<uint32_t*>(&h2);
            pk.w = *reinterpret_cast<uint32_t*>(&h3);
            __half* dst = (h < 2) ? &g_C16[h][item * NH + hbase]
                                  : &g_Cp16[item * NH + hbase];
            *reinterpret_cast<uint4*>(dst) = pk;
        }
    } else if (bx < 942) {
        float (*eu_s)[65] = reinterpret_cast<float(*)[65]>(pbuf);
        float* inv = reinterpret_cast<float*>(pbuf + 16640);
        for (int idx = tid; idx < NB * ND; idx += 256) {
            int b = idx >> 6, d = idx & 63;
            eu_s[b][d] = ue[users[b] * ND + d];
        }
        __syncthreads();
        int blk = bx - 939;
        if (blk < 2) {
            const float* W0 = (blk == 0) ? lW0 : rW0;
            const float* b0 = (blk == 0) ? lb0 : rb0;
            for (int o = tid; o < NB * NH; o += 256) {
                int b = o >> 7, h = o & 127;
                float acc = b0[h];
#pragma unroll
                for (int d = 0; d < ND; d++)
                    acc += eu_s[b][d] * W0[d * NH + h];
                g_au16[blk][o] = __float2half(acc);
            }
        } else {
            for (int b = tid; b < NB; b += 256) {
                float s = 0.f;
#pragma unroll
                for (int d = 0; d < ND; d++) { float v = eu_s[b][d]; s += v * v; }
                inv[b] = rsqrtf(fmaxf(s, 1e-12f));
            }
            __syncthreads();
            for (int o = tid; o < NB * NB; o += 256) {
                int a = o >> 6, b = o & 63;
                float s = 0.f;
#pragma unroll
                for (int d = 0; d < ND; d++)
                    s += eu_s[a][d] * eu_s[b][d];
                out_sim[o] = -(s * inv[a] * inv[b]);
            }
        }
    } else {
        int base = (bx - 942) * 1024 + tid;
#pragma unroll
        for (int j = 0; j < 4; j++) {
            int idx = base + j * 256;
            if (idx < 3 * NH * NH) {
                int h = idx / (NH * NH);
                int rem = idx - h * NH * NH;
                const float* W = (h == 0) ? lW1 : (h == 1) ? rW1 : pW1;
                g_W16[h][rem] = __float2half(W[rem]);
            }
        }
    }
}

// ---------------------------------------------------------------------------
// A-tile builder (fp16 in, fp16 out): 128 rows x 128 k into As (stride 136)
// heads: rows = 8 users x 16 items, A = relu(au16 + C16); popular: C_pop16
// ---------------------------------------------------------------------------
__device__ __forceinline__ void build_A(__half* __restrict__ dst, int head,
                                        int b0u, int tt, int tid)
{
    const __half2 z2 = __floats2half2_rn(0.f, 0.f);
    if (head < 2) {
        int i0 = tt * 16;
        for (int idx = tid; idx < 4096; idx += 256) {
            int r = idx >> 5;
            int k = (idx & 31) << 2;
            int b = b0u + (r & 7);
            int ii = i0 + (r >> 3);
            uint2 cv = *reinterpret_cast<const uint2*>(&g_C16[head][ii * NH + k]);
            uint2 av = *reinterpret_cast<const uint2*>(&g_au16[head][b * NH + k]);
            __half2 s0 = __hmax2(__hadd2(*reinterpret_cast<__half2*>(&cv.x),
                                         *reinterpret_cast<__half2*>(&av.x)), z2);
            __half2 s1 = __hmax2(__hadd2(*reinterpret_cast<__half2*>(&cv.y),
                                         *reinterpret_cast<__half2*>(&av.y)), z2);
            uint2 p;
            p.x = *reinterpret_cast<uint32_t*>(&s0);
            p.y = *reinterpret_cast<uint32_t*>(&s1);
            *reinterpret_cast<uint2*>(&dst[r * 136 + k]) = p;
        }
    } else {
        int i0 = tt * 128;
        for (int idx = tid; idx < 4096; idx += 256) {
            int r = idx >> 5;
            int k = (idx & 31) << 2;
            int ii = i0 + r;
            uint2 p = (ii < NI)
                ? *reinterpret_cast<const uint2*>(&g_Cp16[ii * NH + k])
                : make_uint2(0u, 0u);
            *reinterpret_cast<uint2*>(&dst[r * 136 + k]) = p;
        }
    }
}

// ---------------------------------------------------------------------------
// main_mma: multi-tile fused GEMM. Each block: one (head, user-tile), loops
// over T_TILES item tiles. B/params resident; A double-buffered; 1 sync/tile.
// ---------------------------------------------------------------------------
__global__ __launch_bounds__(256, 2) void main_mma(
    const float* __restrict__ lb1, const float* __restrict__ lW2, const float* __restrict__ lb2,
    const float* __restrict__ rb1, const float* __restrict__ rW2, const float* __restrict__ rb2,
    const float* __restrict__ pb1, const float* __restrict__ pW2, const float* __restrict__ pb2,
    float* __restrict__ out)
{
    extern __shared__ char dynsmem[];
    __half* As = reinterpret_cast<__half*>(dynsmem);          // 2 x (128*136)
    __half* Bs = As + 2 * 128 * 136;                          // 128*136
    float* zpart = reinterpret_cast<float*>(Bs + 128 * 136);  // 2 x 512
    float* b1s = zpart + 1024;
    float* w2s = b1s + 128;
    float* b2sp = w2s + 128;

    int tid = threadIdx.x;
    int warp = tid >> 5, lane = tid & 31;
    int warpM = warp >> 2, warpN = warp & 3;
    int m_base = warpM * 64, n_base = warpN * 32;
    int bx = blockIdx.x;

    int head, b0u = 0, t0, nt;
    const float *b1, *W2, *b2;
    if (bx < 2000) {
        head = bx / 1000;
        int rem = bx - head * 1000;
        b0u = (rem / 125) * 8;
        t0 = (rem % 125) * T_TILES;
        nt = T_TILES;
        if (head == 0) { b1 = lb1; W2 = lW2; b2 = lb2; }
        else           { b1 = rb1; W2 = rW2; b2 = rb2; }
    } else {
        head = 2;
        t0 = (bx - 2000) * T_TILES;
        nt = min(T_TILES, 157 - t0);
        b1 = pb1; W2 = pW2; b2 = pb2;
    }

    if (tid < 128) { b1s[tid] = b1[tid]; w2s[tid] = W2[tid]; }
    if (tid == 0) b2sp[0] = b2[0];

    // Load full B once (fp16 [k][n] -> Bs stride 136)
    {
        const __half* Wsrc = g_W16[head];
        for (int idx = tid; idx < 4096; idx += 256) {
            int kk = idx >> 5;
            int n4 = (idx & 31) << 2;
            uint2 v = *reinterpret_cast<const uint2*>(&Wsrc[kk * NH + n4]);
            *reinterpret_cast<uint2*>(&Bs[kk * 136 + n4]) = v;
        }
    }
    // Build first A tile into buffer 0
    build_A(As, head, b0u, t0, tid);
    __syncthreads();

    int arow = lane & 15;
    int acol_off = (lane >> 4) << 3;
    int g = lane >> 2, tq = lane & 3;
    int bgrp = lane >> 3;
    int brow_off = ((bgrp & 1) << 3) + (lane & 7);
    int bcol_off = (bgrp >> 1) << 3;

    int p = 0;
    for (int t = 0; t < nt; t++) {
        int tt = t0 + t;
        const __half* Ab = As + p * (128 * 136);

        float acc[4][4][4];
#pragma unroll
        for (int f = 0; f < 4; f++)
#pragma unroll
            for (int g2 = 0; g2 < 4; g2++)
#pragma unroll
                for (int q = 0; q < 4; q++) acc[f][g2][q] = 0.f;

        // ---- 8 k-steps of m16n8k16 ----
#pragma unroll
        for (int ks = 0; ks < 8; ks++) {
            int kA = (ks << 4) + acol_off;
            uint32_t afr[4][4];
#pragma unroll
            for (int f = 0; f < 4; f++)
                ldsm_x4(afr[f], smem_u32(&Ab[(m_base + f * 16 + arow) * 136 + kA]));
            // B: two x4.trans ops cover 4 col-groups of 8
            uint32_t bfr[4][2];
            int brow = (ks << 4) + brow_off;
#pragma unroll
            for (int pr = 0; pr < 2; pr++) {
                uint32_t tmp[4];
                int bcol = n_base + (pr << 4) + bcol_off;
                ldsm_x4_trans(tmp, smem_u32(&Bs[brow * 136 + bcol]));
                bfr[2 * pr][0] = tmp[0]; bfr[2 * pr][1] = tmp[1];
                bfr[2 * pr + 1][0] = tmp[2]; bfr[2 * pr + 1][1] = tmp[3];
            }
#pragma unroll
            for (int f = 0; f < 4; f++)
#pragma unroll
                for (int g2 = 0; g2 < 4; g2++)
                    mma_fp16(acc[f][g2], afr[f], bfr[g2], acc[f][g2]);
        }

        // ---- Prefetch-build next A tile into other buffer ----
        if (t + 1 < nt)
            build_A(As + (p ^ 1) * (128 * 136), head, b0u, tt + 1, tid);

        // ---- Epilogue partials ----
        float* zp = zpart + p * 512;
#pragma unroll
        for (int f = 0; f < 4; f++) {
            float z0 = 0.f, z1 = 0.f;
#pragma unroll
            for (int nf = 0; nf < 4; nf++) {
                int col = n_base + nf * 8 + tq * 2;
                float b10 = b1s[col], b11 = b1s[col + 1];
                float w0 = w2s[col], w1 = w2s[col + 1];
                z0 += fmaxf(acc[f][nf][0] + b10, 0.f) * w0 + fmaxf(acc[f][nf][1] + b11, 0.f) * w1;
                z1 += fmaxf(acc[f][nf][2] + b10, 0.f) * w0 + fmaxf(acc[f][nf][3] + b11, 0.f) * w1;
            }
            z0 += __shfl_xor_sync(0xffffffffu, z0, 1);
            z0 += __shfl_xor_sync(0xffffffffu, z0, 2);
            z1 += __shfl_xor_sync(0xffffffffu, z1, 1);
            z1 += __shfl_xor_sync(0xffffffffu, z1, 2);
            if (tq == 0) {
                zp[warpN * 128 + m_base + f * 16 + g] = z0;
                zp[warpN * 128 + m_base + f * 16 + g + 8] = z1;
            }
        }
        __syncthreads();   // zpart ready + next A ready

        if (tid < 128) {
            if (head < 2) {
                // coalesced: 16 consecutive tids -> 16 consecutive items of one user
                int r = ((tid & 15) << 3) | (tid >> 4);
                float z = zp[r] + zp[128 + r] + zp[256 + r] + zp[384 + r] + b2sp[0];
                float s = 1.f / (1.f + __expf(-z));
                int b = b0u + (tid >> 4);
                int i = tt * 16 + (tid & 15);
                out[(head ? OFF_RATED : OFF_LIKES) + b * NI + i] = s;
            } else {
                float z = zp[tid] + zp[128 + tid] + zp[256 + tid] + zp[384 + tid] + b2sp[0];
                float s = 1.f / (1.f + __expf(-z));
                int i = tt * 128 + tid;
                if (i < NI) out[OFF_POP + i] = s;
            }
        }
        p ^= 1;
    }
}

// ---------------------------------------------------------------------------
extern "C" void kernel_launch(void* const* d_in, const int* in_sizes, int n_in,
                              void* d_out, int out_size)
{
    const int*   users = (const int*)  d_in[0];
    const float* ue    = (const float*)d_in[1];
    const float* ie    = (const float*)d_in[2];
    const float* lW0 = (const float*)d_in[3];
    const float* lb0 = (const float*)d_in[4];
    const float* lW1 = (const float*)d_in[5];
    const float* lb1 = (const float*)d_in[6];
    const float* lW2 = (const float*)d_in[7];
    const float* lb2 = (const float*)d_in[8];
    const float* rW0 = (const float*)d_in[9];
    const float* rb0 = (const float*)d_in[10];
    const float* rW1 = (const float*)d_in[11];
    const float* rb1 = (const float*)d_in[12];
    const float* rW2 = (const float*)d_in[13];
    const float* rb2 = (const float*)d_in[14];
    const float* pW0 = (const float*)d_in[15];
    const float* pb0 = (const float*)d_in[16];
    const float* pW1 = (const float*)d_in[17];
    const float* pb1 = (const float*)d_in[18];
    const float* pW2 = (const float*)d_in[19];
    const float* pb2 = (const float*)d_in[20];
    float* out = (float*)d_out;

    cudaFuncSetAttribute(main_mma, cudaFuncAttributeMaxDynamicSharedMemorySize,
                         SMEM_BYTES);

    prep_all<<<990, 256>>>(users, ue, ie,
                           lW0, lb0, rW0, rb0, pW0, pb0,
                           lW1, rW1, pW1,
                           out + OFF_SIM);
    main_mma<<<GRID_MAIN, 256, SMEM_BYTES>>>(lb1, lW2, lb2,
                                             rb1, rW2, rb2,
                                             pb1, pW2, pb2,
                                             out);
}

// round 11
// speedup vs baseline: 6.5782x; 1.1223x over previous
#include <cuda_runtime.h>
#include <cuda_fp16.h>
#include <math.h>
#include <stdint.h>

// Problem constants
#define NU 100000
#define NI 20000
#define ND 64
#define NH 128
#define NB 64

// Output layout (flattened concat of the returned tuple)
#define OFF_LIKES 0
#define OFF_SIM   1280000
#define OFF_RATED 1284096
#define OFF_POP   2564096

#define N_WORK 20157        // 20000 head tiles + 157 popular tiles
#define GRID_MAIN 296       // 148 SMs x 2 CTAs: one wave, persistent chunks

// Scratch (device globals — no allocation allowed)
__device__ __half g_au16[2][NB * NH];   // per-head: fp16(eu@Wu + b0)
__device__ __half g_C16[2][NI * NH];    // per-head: fp16(ei@Wi)
__device__ __half g_Cp16[NI * NH];      // popular: fp16(relu(ei@pW0 + pb0))
__device__ __half g_W16[3][NH * NH];    // W1 per head, fp16, [k][n]

// Dynamic smem (main_mma):
//   As: 2 * 128*136 half  (69632 B)
//   Bs: 128*136 half      (34816 B)
//   zpart: 2*512 float    (4096 B)
//   b1s,w2s: 128+128 float, pad
#define SMEM_BYTES (69632 + 34816 + 4096 + 512 + 512 + 16)

// ---------------------------------------------------------------------------
// PTX helpers
// ---------------------------------------------------------------------------
__device__ __forceinline__ uint32_t smem_u32(const void* p) {
    return (uint32_t)__cvta_generic_to_shared(p);
}
__device__ __forceinline__ void ldsm_x4(uint32_t* r, uint32_t addr) {
    asm volatile("ldmatrix.sync.aligned.m8n8.x4.shared.b16 {%0,%1,%2,%3}, [%4];"
        : "=r"(r[0]), "=r"(r[1]), "=r"(r[2]), "=r"(r[3]) : "r"(addr));
}
__device__ __forceinline__ void ldsm_x4_trans(uint32_t* r, uint32_t addr) {
    asm volatile("ldmatrix.sync.aligned.m8n8.x4.trans.shared.b16 {%0,%1,%2,%3}, [%4];"
        : "=r"(r[0]), "=r"(r[1]), "=r"(r[2]), "=r"(r[3]) : "r"(addr));
}
__device__ __forceinline__ void mma_fp16(float* d, const uint32_t* a,
                                         const uint32_t* b, const float* c) {
    asm volatile("mma.sync.aligned.m16n8k16.row.col.f32.f16.f16.f32 "
        "{%0,%1,%2,%3}, {%4,%5,%6,%7}, {%8,%9}, {%10,%11,%12,%13};"
        : "=f"(d[0]), "=f"(d[1]), "=f"(d[2]), "=f"(d[3])
        : "r"(a[0]), "r"(a[1]), "r"(a[2]), "r"(a[3]),
          "r"(b[0]), "r"(b[1]),
          "f"(c[0]), "f"(c[1]), "f"(c[2]), "f"(c[3]));
}
__device__ __forceinline__ __half2 u2h(uint32_t v) {
    return *reinterpret_cast<__half2*>(&v);
}
__device__ __forceinline__ uint32_t h2u(__half2 v) {
    return *reinterpret_cast<uint32_t*>(&v);
}

// ---------------------------------------------------------------------------
// prep_all: heterogeneous blocks (unchanged from round 10).
// ---------------------------------------------------------------------------
__global__ __launch_bounds__(256) void prep_all(
    const int* __restrict__ users, const float* __restrict__ ue,
    const float* __restrict__ ie,
    const float* __restrict__ lW0, const float* __restrict__ lb0,
    const float* __restrict__ rW0, const float* __restrict__ rb0,
    const float* __restrict__ pW0, const float* __restrict__ pb0,
    const float* __restrict__ lW1, const float* __restrict__ rW1,
    const float* __restrict__ pW1,
    float* __restrict__ out_sim)
{
    __shared__ __align__(16) char pbuf[33024];
    int bx = blockIdx.x;
    int tid = threadIdx.x;

    if (bx < 939) {
        int h = bx / 313;
        int blk = bx - h * 313;
        float (*eiN)[65]  = reinterpret_cast<float(*)[65]>(pbuf);
        float (*w0s)[128] = reinterpret_cast<float(*)[128]>(pbuf + 16640);
        int i0 = blk * 64;
        int tx = tid & 15, ty = tid >> 4;

        for (int idx = tid; idx < 4096; idx += 256) {
            int it = idx >> 6, d = idx & 63;
            int i = i0 + it;
            eiN[it][d] = (i < NI) ? ie[i * ND + d] : 0.f;
        }

        const float* W0 = (h == 0) ? lW0 : (h == 1) ? rW0 : pW0;
        int roff = (h < 2) ? ND : 0;

        float acc[4][8];
#pragma unroll
        for (int i = 0; i < 4; i++)
#pragma unroll
            for (int j = 0; j < 8; j++) acc[i][j] = 0.f;

        for (int ch = 0; ch < 2; ch++) {
            __syncthreads();
            for (int idx = tid; idx < 1024; idx += 256) {
                int d = idx >> 5, c4 = (idx & 31) << 2;
                *reinterpret_cast<float4*>(&w0s[d][c4]) =
                    *reinterpret_cast<const float4*>(&W0[(roff + ch * 32 + d) * NH + c4]);
            }
            __syncthreads();
#pragma unroll 8
            for (int d = 0; d < 32; d++) {
                int dd = ch * 32 + d;
                float e0 = eiN[ty * 4 + 0][dd];
                float e1 = eiN[ty * 4 + 1][dd];
                float e2 = eiN[ty * 4 + 2][dd];
                float e3 = eiN[ty * 4 + 3][dd];
                float4 wa = *reinterpret_cast<float4*>(&w0s[d][tx * 8]);
                float4 wb = *reinterpret_cast<float4*>(&w0s[d][tx * 8 + 4]);
                float w[8] = {wa.x, wa.y, wa.z, wa.w, wb.x, wb.y, wb.z, wb.w};
#pragma unroll
                for (int j = 0; j < 8; j++) {
                    acc[0][j] += e0 * w[j];
                    acc[1][j] += e1 * w[j];
                    acc[2][j] += e2 * w[j];
                    acc[3][j] += e3 * w[j];
                }
            }
        }

        int hbase = tx * 8;
#pragma unroll
        for (int i = 0; i < 4; i++) {
            int item = i0 + ty * 4 + i;
            if (item >= NI) continue;
            float v[8];
#pragma unroll
            for (int j = 0; j < 8; j++) {
                float a = acc[i][j];
                if (h == 2) a = fmaxf(a + pb0[hbase + j], 0.f);
                v[j] = a;
            }
            __half2 h0 = __floats2half2_rn(v[0], v[1]);
            __half2 h1 = __floats2half2_rn(v[2], v[3]);
            __half2 h2c = __floats2half2_rn(v[4], v[5]);
            __half2 h3 = __floats2half2_rn(v[6], v[7]);
            uint4 pk;
            pk.x = h2u(h0); pk.y = h2u(h1); pk.z = h2u(h2c); pk.w = h2u(h3);
            __half* dst = (h < 2) ? &g_C16[h][item * NH + hbase]
                                  : &g_Cp16[item * NH + hbase];
            *reinterpret_cast<uint4*>(dst) = pk;
        }
    } else if (bx < 942) {
        float (*eu_s)[65] = reinterpret_cast<float(*)[65]>(pbuf);
        float* inv = reinterpret_cast<float*>(pbuf + 16640);
        for (int idx = tid; idx < NB * ND; idx += 256) {
            int b = idx >> 6, d = idx & 63;
            eu_s[b][d] = ue[users[b] * ND + d];
        }
        __syncthreads();
        int blk = bx - 939;
        if (blk < 2) {
            const float* W0 = (blk == 0) ? lW0 : rW0;
            const float* b0 = (blk == 0) ? lb0 : rb0;
            for (int o = tid; o < NB * NH; o += 256) {
                int b = o >> 7, h = o & 127;
                float acc = b0[h];
#pragma unroll
                for (int d = 0; d < ND; d++)
                    acc += eu_s[b][d] * W0[d * NH + h];
                g_au16[blk][o] = __float2half(acc);
            }
        } else {
            for (int b = tid; b < NB; b += 256) {
                float s = 0.f;
#pragma unroll
                for (int d = 0; d < ND; d++) { float v = eu_s[b][d]; s += v * v; }
                inv[b] = rsqrtf(fmaxf(s, 1e-12f));
            }
            __syncthreads();
            for (int o = tid; o < NB * NB; o += 256) {
                int a = o >> 6, b = o & 63;
                float s = 0.f;
#pragma unroll
                for (int d = 0; d < ND; d++)
                    s += eu_s[a][d] * eu_s[b][d];
                out_sim[o] = -(s * inv[a] * inv[b]);
            }
        }
    } else {
        int base = (bx - 942) * 1024 + tid;
#pragma unroll
        for (int j = 0; j < 4; j++) {
            int idx = base + j * 256;
            if (idx < 3 * NH * NH) {
                int h = idx / (NH * NH);
                int rem = idx - h * NH * NH;
                const float* W = (h == 0) ? lW1 : (h == 1) ? rW1 : pW1;
                g_W16[h][rem] = __float2half(W[rem]);
            }
        }
    }
}

// ---------------------------------------------------------------------------
// Work decode: tile index w -> (head, user-tile base, item base)
// ---------------------------------------------------------------------------
__device__ __forceinline__ void decode_w(int w, int& head, int& b0u, int& i0) {
    if (w < 20000) {
        head = w / 10000;
        int rem = w - head * 10000;
        b0u = (rem / 1250) * 8;
        i0 = (rem % 1250) * 16;
    } else {
        head = 2;
        b0u = 0;
        i0 = (w - 20000) * 128;
    }
}

// ---------------------------------------------------------------------------
// A-tile builder: uint4 loads, fully unrolled (8 iterations / thread)
// ---------------------------------------------------------------------------
__device__ __forceinline__ void build_A(__half* __restrict__ dst, int head,
                                        int b0u, int i0, int tid)
{
    const __half2 z2 = __floats2half2_rn(0.f, 0.f);
    if (head < 2) {
#pragma unroll
        for (int it = 0; it < 8; it++) {
            int idx = tid + it * 256;
            int r = idx >> 4;
            int kc = (idx & 15) << 3;
            int b = b0u + (r & 7);
            int ii = i0 + (r >> 3);
            uint4 cv = *reinterpret_cast<const uint4*>(&g_C16[head][ii * NH + kc]);
            uint4 av = *reinterpret_cast<const uint4*>(&g_au16[head][b * NH + kc]);
            uint4 p;
            p.x = h2u(__hmax2(__hadd2(u2h(cv.x), u2h(av.x)), z2));
            p.y = h2u(__hmax2(__hadd2(u2h(cv.y), u2h(av.y)), z2));
            p.z = h2u(__hmax2(__hadd2(u2h(cv.z), u2h(av.z)), z2));
            p.w = h2u(__hmax2(__hadd2(u2h(cv.w), u2h(av.w)), z2));
            *reinterpret_cast<uint4*>(&dst[r * 136 + kc]) = p;
        }
    } else {
#pragma unroll
        for (int it = 0; it < 8; it++) {
            int idx = tid + it * 256;
            int r = idx >> 4;
            int kc = (idx & 15) << 3;
            int ii = i0 + r;
            uint4 p = (ii < NI)
                ? *reinterpret_cast<const uint4*>(&g_Cp16[ii * NH + kc])
                : make_uint4(0u, 0u, 0u, 0u);
            *reinterpret_cast<uint4*>(&dst[r * 136 + kc]) = p;
        }
    }
}

// ---------------------------------------------------------------------------
// main_mma: persistent blocks. 296 blocks, each owns a contiguous chunk of
// the 20157 tiles. Head-dependent state (B, b1, w2) reloaded only on head
// boundary crossings (2 blocks globally).
// ---------------------------------------------------------------------------
__global__ __launch_bounds__(256, 2) void main_mma(
    const float* __restrict__ lb1, const float* __restrict__ lW2, const float* __restrict__ lb2,
    const float* __restrict__ rb1, const float* __restrict__ rW2, const float* __restrict__ rb2,
    const float* __restrict__ pb1, const float* __restrict__ pW2, const float* __restrict__ pb2,
    float* __restrict__ out)
{
    extern __shared__ char dynsmem[];
    __half* As = reinterpret_cast<__half*>(dynsmem);          // 2 x (128*136)
    __half* Bs = As + 2 * 128 * 136;                          // 128*136
    float* zpart = reinterpret_cast<float*>(Bs + 128 * 136);  // 2 x 512
    float* b1s = zpart + 1024;
    float* w2s = b1s + 128;

    int tid = threadIdx.x;
    int warp = tid >> 5, lane = tid & 31;
    int warpM = warp >> 2, warpN = warp & 3;
    int m_base = warpM * 64, n_base = warpN * 32;
    int bid = blockIdx.x;

    // Chunk bounds (balanced): base=68, first 29 blocks get 69
    int cbase = N_WORK / GRID_MAIN;
    int crem  = N_WORK % GRID_MAIN;
    int w0 = bid * cbase + min(bid, crem);
    int w1 = w0 + cbase + (bid < crem ? 1 : 0);

    const float* b1tab[3] = {lb1, rb1, pb1};
    const float* w2tab[3] = {lW2, rW2, pW2};
    const float* b2tab[3] = {lb2, rb2, pb2};

    int head, b0u, i0;
    decode_w(w0, head, b0u, i0);

    // Load head state: b1s, w2s, Bs
    {
        const float* b1 = b1tab[head];
        const float* W2 = w2tab[head];
        if (tid < 128) { b1s[tid] = b1[tid]; w2s[tid] = W2[tid]; }
        const __half* Wsrc = g_W16[head];
#pragma unroll
        for (int it = 0; it < 8; it++) {
            int idx = tid + it * 256;
            int kk = idx >> 4;
            int n8 = (idx & 15) << 3;
            uint4 v = *reinterpret_cast<const uint4*>(&Wsrc[kk * NH + n8]);
            *reinterpret_cast<uint4*>(&Bs[kk * 136 + n8]) = v;
        }
    }
    build_A(As, head, b0u, i0, tid);
    __syncthreads();

    int arow = lane & 15;
    int acol_off = (lane >> 4) << 3;
    int g = lane >> 2, tq = lane & 3;
    int bgrp = lane >> 3;
    int brow_off = ((bgrp & 1) << 3) + (lane & 7);
    int bcol_off = (bgrp >> 1) << 3;

    int p = 0;
    for (int w = w0; w < w1; w++) {
        const __half* Ab = As + p * (128 * 136);

        float acc[4][4][4];
#pragma unroll
        for (int f = 0; f < 4; f++)
#pragma unroll
            for (int g2 = 0; g2 < 4; g2++)
#pragma unroll
                for (int q = 0; q < 4; q++) acc[f][g2][q] = 0.f;

        // ---- 8 k-steps of m16n8k16 ----
#pragma unroll
        for (int ks = 0; ks < 8; ks++) {
            int kA = (ks << 4) + acol_off;
            uint32_t afr[4][4];
#pragma unroll
            for (int f = 0; f < 4; f++)
                ldsm_x4(afr[f], smem_u32(&Ab[(m_base + f * 16 + arow) * 136 + kA]));
            uint32_t bfr[4][2];
            int brow = (ks << 4) + brow_off;
#pragma unroll
            for (int pr = 0; pr < 2; pr++) {
                uint32_t tmp[4];
                int bcol = n_base + (pr << 4) + bcol_off;
                ldsm_x4_trans(tmp, smem_u32(&Bs[brow * 136 + bcol]));
                bfr[2 * pr][0] = tmp[0]; bfr[2 * pr][1] = tmp[1];
                bfr[2 * pr + 1][0] = tmp[2]; bfr[2 * pr + 1][1] = tmp[3];
            }
#pragma unroll
            for (int f = 0; f < 4; f++)
#pragma unroll
                for (int g2 = 0; g2 < 4; g2++)
                    mma_fp16(acc[f][g2], afr[f], bfr[g2], acc[f][g2]);
        }

        // ---- Prefetch-build next A into other buffer ----
        bool have_next = (w + 1 < w1);
        int nhead = head, nb0u = b0u, ni0 = i0;
        if (have_next) {
            decode_w(w + 1, nhead, nb0u, ni0);
            build_A(As + (p ^ 1) * (128 * 136), nhead, nb0u, ni0, tid);
        }

        // ---- Epilogue partials ----
        float* zp = zpart + p * 512;
#pragma unroll
        for (int f = 0; f < 4; f++) {
            float z0 = 0.f, z1 = 0.f;
#pragma unroll
            for (int nf = 0; nf < 4; nf++) {
                int col = n_base + nf * 8 + tq * 2;
                float b10 = b1s[col], b11 = b1s[col + 1];
                float ww0 = w2s[col], ww1 = w2s[col + 1];
                z0 += fmaxf(acc[f][nf][0] + b10, 0.f) * ww0 + fmaxf(acc[f][nf][1] + b11, 0.f) * ww1;
                z1 += fmaxf(acc[f][nf][2] + b10, 0.f) * ww0 + fmaxf(acc[f][nf][3] + b11, 0.f) * ww1;
            }
            z0 += __shfl_xor_sync(0xffffffffu, z0, 1);
            z0 += __shfl_xor_sync(0xffffffffu, z0, 2);
            z1 += __shfl_xor_sync(0xffffffffu, z1, 1);
            z1 += __shfl_xor_sync(0xffffffffu, z1, 2);
            if (tq == 0) {
                zp[warpN * 128 + m_base + f * 16 + g] = z0;
                zp[warpN * 128 + m_base + f * 16 + g + 8] = z1;
            }
        }
        __syncthreads();   // zpart ready + next A ready; all MMA(w) done

        // ---- Final stores for w ----
        if (tid < 128) {
            float b2v = b2tab[head][0];
            if (head < 2) {
                int r = ((tid & 15) << 3) | (tid >> 4);
                float z = zp[r] + zp[128 + r] + zp[256 + r] + zp[384 + r] + b2v;
                float s = 1.f / (1.f + __expf(-z));
                int b = b0u + (tid >> 4);
                int i = i0 + (tid & 15);
                out[(head ? OFF_RATED : OFF_LIKES) + b * NI + i] = s;
            } else {
                float z = zp[tid] + zp[128 + tid] + zp[256 + tid] + zp[384 + tid] + b2v;
                float s = 1.f / (1.f + __expf(-z));
                int i = i0 + tid;
                if (i < NI) out[OFF_POP + i] = s;
            }
        }

        // ---- Head boundary: reload B/b1/w2 (rare: 2 blocks globally) ----
        if (have_next && nhead != head) {
            const float* b1 = b1tab[nhead];
            const float* W2 = w2tab[nhead];
            if (tid < 128) { b1s[tid] = b1[tid]; w2s[tid] = W2[tid]; }
            const __half* Wsrc = g_W16[nhead];
#pragma unroll
            for (int it = 0; it < 8; it++) {
                int idx = tid + it * 256;
                int kk = idx >> 4;
                int n8 = (idx & 15) << 3;
                uint4 v = *reinterpret_cast<const uint4*>(&Wsrc[kk * NH + n8]);
                *reinterpret_cast<uint4*>(&Bs[kk * 136 + n8]) = v;
            }
            __syncthreads();   // Bs/b1s/w2s ready before MMA(w+1)
        }

        head = nhead; b0u = nb0u; i0 = ni0;
        p ^= 1;
    }
}

// ---------------------------------------------------------------------------
extern "C" void kernel_launch(void* const* d_in, const int* in_sizes, int n_in,
                              void* d_out, int out_size)
{
    const int*   users = (const int*)  d_in[0];
    const float* ue    = (const float*)d_in[1];
    const float* ie    = (const float*)d_in[2];
    const float* lW0 = (const float*)d_in[3];
    const float* lb0 = (const float*)d_in[4];
    const float* lW1 = (const float*)d_in[5];
    const float* lb1 = (const float*)d_in[6];
    const float* lW2 = (const float*)d_in[7];
    const float* lb2 = (const float*)d_in[8];
    const float* rW0 = (const float*)d_in[9];
    const float* rb0 = (const float*)d_in[10];
    const float* rW1 = (const float*)d_in[11];
    const float* rb1 = (const float*)d_in[12];
    const float* rW2 = (const float*)d_in[13];
    const float* rb2 = (const float*)d_in[14];
    const float* pW0 = (const float*)d_in[15];
    const float* pb0 = (const float*)d_in[16];
    const float* pW1 = (const float*)d_in[17];
    const float* pb1 = (const float*)d_in[18];
    const float* pW2 = (const float*)d_in[19];
    const float* pb2 = (const float*)d_in[20];
    float* out = (float*)d_out;

    cudaFuncSetAttribute(main_mma, cudaFuncAttributeMaxDynamicSharedMemorySize,
                         SMEM_BYTES);

    prep_all<<<990, 256>>>(users, ue, ie,
                           lW0, lb0, rW0, rb0, pW0, pb0,
                           lW1, rW1, pW1,
                           out + OFF_SIM);
    main_mma<<<GRID_MAIN, 256, SMEM_BYTES>>>(lb1, lW2, lb2,
                                             rb1, rW2, rb2,
                                             pb1, pW2, pb2,
                                             out);
}